// round 9
// baseline (speedup 1.0000x reference)
#include <cuda_runtime.h>
#include <cstdint>

typedef unsigned long long ull;

#define B_ 16
#define S_ 16384
#define C_ 256
#define NH_ 8
#define VD_ 64
#define CHB 18                            /* chunks per batch */
#define NCTA (B_ * CHB)                   /* 288 = 2 CTAs per SM, one wave */
#define PART_STRIDE 2080                  /* 2048 acc + 4 warps x 8 sums */
#define GROUPS_PER_B 512                  /* 32-row groups per batch */
#define NSTAGE 3
#define PREFETCH 2
#define STAGE_ROWS 32
#define STAGE_BYTES (STAGE_ROWS * C_ * 4) /* 32768 */
#define LOG2E 1.4426950408889634f

/* dynamic smem layout */
#define SMW_OFF  (NSTAGE * STAGE_BYTES)               /* 98304: weights 3*4*4*8 ull = 3072B */
#define MBAR_OFF (SMW_OFF + 3072)                     /* 101376: 9 mbarriers */
#define SMEM_TOTAL (MBAR_OFF + 128)                   /* 101504 */

// Device-global scratch (no runtime allocation allowed).
__device__ __align__(16) float g_wqT[NH_ * C_];                  // (Wk @ q) * log2e, [h][c]
__device__ __align__(16) float g_part[(size_t)NCTA * PART_STRIDE];
__device__ int g_done[B_];                                       // zero-init; winner resets

// ---------------- packed f32x2 helpers ----------------
__device__ __forceinline__ ull f2fma(ull a, ull b, ull c) {
    ull d; asm("fma.rn.f32x2 %0,%1,%2,%3;" : "=l"(d) : "l"(a), "l"(b), "l"(c)); return d;
}
__device__ __forceinline__ ull f2mul(ull a, ull b) {
    ull d; asm("mul.rn.f32x2 %0,%1,%2;" : "=l"(d) : "l"(a), "l"(b)); return d;
}
__device__ __forceinline__ ull f2add(ull a, ull b) {
    ull d; asm("add.rn.f32x2 %0,%1,%2;" : "=l"(d) : "l"(a), "l"(b)); return d;
}
__device__ __forceinline__ ull pk(float x, float y) {
    ull r; asm("mov.b64 %0,{%1,%2};" : "=l"(r) : "f"(x), "f"(y)); return r;
}
__device__ __forceinline__ float2 upk(ull v) {
    float2 r; asm("mov.b64 {%0,%1},%2;" : "=f"(r.x), "=f"(r.y) : "l"(v)); return r;
}
__device__ __forceinline__ ull shx64(ull v, int m) {
    unsigned lo, hi;
    asm("mov.b64 {%0,%1},%2;" : "=r"(lo), "=r"(hi) : "l"(v));
    lo = __shfl_xor_sync(0xffffffffu, lo, m);
    hi = __shfl_xor_sync(0xffffffffu, hi, m);
    ull r; asm("mov.b64 %0,{%1,%2};" : "=l"(r) : "r"(lo), "r"(hi)); return r;
}

__device__ __forceinline__ uint32_t smem_u32(const void* p) {
    uint32_t a;
    asm("{ .reg .u64 t; cvta.to.shared.u64 t, %1; cvt.u32.u64 %0, t; }" : "=r"(a) : "l"(p));
    return a;
}

// ---------------- mbarrier / bulk-copy primitives ----------------
#define MBARRIER_INIT(mbar, cnt) \
    asm volatile("mbarrier.init.shared.b64 [%0], %1;" :: "r"(mbar), "r"((uint32_t)(cnt)) : "memory")
#define MBARRIER_ARRIVE(mbar) \
    asm volatile("mbarrier.arrive.shared.b64 _, [%0];" :: "r"(mbar) : "memory")
#define MBARRIER_EXPECT_TX(mbar, bytes) \
    asm volatile("mbarrier.arrive.expect_tx.shared.b64 _, [%0], %1;" :: "r"(mbar), "r"((uint32_t)(bytes)) : "memory")

#define MBARRIER_WAIT_PARITY(mbar, par) do {                                            \
    uint32_t _m = (mbar), _p = (uint32_t)(par), _done;                                  \
    asm volatile("{\n\t.reg .pred p;\n\t"                                               \
        "mbarrier.try_wait.parity.acquire.cta.shared::cta.b64 p, [%1], %2;\n\t"         \
        "selp.b32 %0, 1, 0, p;\n\t}"                                                    \
        : "=r"(_done) : "r"(_m), "r"(_p) : "memory");                                   \
    if (!_done) {                                                                       \
        asm volatile("{\n\t.reg .pred P1;\n\t"                                          \
            "WL_%=:\n\t"                                                                \
            "mbarrier.try_wait.parity.acquire.cta.shared::cta.b64 P1, [%0], %1, 0x989680;\n\t" \
            "@P1 bra.uni WD_%=;\n\t"                                                    \
            "bra.uni WL_%=;\n\t"                                                        \
            "WD_%=:\n\t}"                                                               \
            :: "r"(_m), "r"(_p) : "memory");                                            \
    }                                                                                   \
} while (0)

#define MBARRIER_WAIT_PARITY_RELAXED(mbar, par) do {                                    \
    uint32_t _m = (mbar), _p = (uint32_t)(par), _done;                                  \
    asm volatile("{\n\t.reg .pred p;\n\t"                                               \
        "mbarrier.try_wait.parity.relaxed.cta.shared::cta.b64 p, [%1], %2, 0x989680;\n\t" \
        "selp.b32 %0, 1, 0, p;\n\t}"                                                    \
        : "=r"(_done) : "r"(_m), "r"(_p) : "memory");                                   \
    if (!_done) {                                                                       \
        asm volatile("{\n\t.reg .pred P1;\n\t"                                          \
            "WL_%=:\n\t"                                                                \
            "mbarrier.try_wait.parity.relaxed.cta.shared::cta.b64 P1, [%0], %1, 0x989680;\n\t" \
            "@P1 bra.uni WD_%=;\n\t"                                                    \
            "bra.uni WL_%=;\n\t"                                                        \
            "WD_%=:\n\t}"                                                               \
            :: "r"(_m), "r"(_p) : "memory");                                            \
    }                                                                                   \
} while (0)

#define BULK_G2S(dst_u32, src_ptr, bytes, mbar) \
    asm volatile("cp.async.bulk.shared::cluster.global.mbarrier::complete_tx::bytes [%0], [%1], %2, [%3];" \
        :: "r"(dst_u32), "l"(src_ptr), "r"((uint32_t)(bytes)), "r"(mbar) : "memory")

// ---------------- staged value-halving reduction levels ----------------
__device__ __forceinline__ void red_l16(ull v[8], int lane) {
    bool hi = (lane & 16) != 0;
#pragma unroll
    for (int j = 0; j < 4; j++) {
        ull snd = hi ? v[j] : v[j + 4];
        ull kp  = hi ? v[j + 4] : v[j];
        v[j] = f2add(kp, shx64(snd, 16));
    }
}
__device__ __forceinline__ void red_l8(ull v[8], int lane) {
    bool hi = (lane & 8) != 0;
#pragma unroll
    for (int j = 0; j < 2; j++) {
        ull snd = hi ? v[j] : v[j + 2];
        ull kp  = hi ? v[j + 2] : v[j];
        v[j] = f2add(kp, shx64(snd, 8));
    }
}
__device__ __forceinline__ void red_l4(ull v[8], int lane) {
    bool hi = (lane & 4) != 0;
    ull snd = hi ? v[0] : v[1];
    ull kp  = hi ? v[1] : v[0];
    v[0] = f2add(kp, shx64(snd, 4));
}

// Conflict-free 2-row load: lane owns c in {4l..4l+3} and {128+4l..128+4l+3}.
__device__ __forceinline__ void load_row(ull out[4], const char* rowp, int lane) {
    ulonglong2 a0 = *reinterpret_cast<const ulonglong2*>(rowp + lane * 16);
    ulonglong2 a1 = *reinterpret_cast<const ulonglong2*>(rowp + 512 + lane * 16);
    out[0] = a0.x; out[1] = a0.y; out[2] = a1.x; out[3] = a1.y;
}

// Score FMA for a 2-row pair -> packed v[8] (per-head, rows in f32x2 lanes).
__device__ __forceinline__ void score_pair(const char* rbase, int r0, int lane,
                                           const ull wq2[4][NH_], ull v[8]) {
    ull kv0[4], kv1[4];
    load_row(kv0, rbase + r0 * 1024, lane);
    load_row(kv1, rbase + (r0 + 1) * 1024, lane);
    float s0[NH_];
    ull p[NH_];
#pragma unroll
    for (int h = 0; h < NH_; h++) p[h] = f2mul(kv0[0], wq2[0][h]);
#pragma unroll
    for (int j2 = 1; j2 < 4; j2++)
#pragma unroll
        for (int h = 0; h < NH_; h++) p[h] = f2fma(kv0[j2], wq2[j2][h], p[h]);
#pragma unroll
    for (int h = 0; h < NH_; h++) { float2 u2 = upk(p[h]); s0[h] = u2.x + u2.y; }
#pragma unroll
    for (int h = 0; h < NH_; h++) p[h] = f2mul(kv1[0], wq2[0][h]);
#pragma unroll
    for (int j2 = 1; j2 < 4; j2++)
#pragma unroll
        for (int h = 0; h < NH_; h++) p[h] = f2fma(kv1[j2], wq2[j2][h], p[h]);
#pragma unroll
    for (int h = 0; h < NH_; h++) { float2 u2 = upk(p[h]); v[h] = pk(s0[h], u2.x + u2.y); }
}

// ---------------- Kernel A: fold Wk @ q -> wq[h][c], scaled by log2e ----------------
__global__ void mha_prep(const float* __restrict__ Wk, const float* __restrict__ q) {
    int w = threadIdx.x >> 5, lane = threadIdx.x & 31;
    int idx = blockIdx.x * 16 + w;   // 0..2047 = h*256 + c
    int h = idx >> 8, c = idx & 255;
    float a = Wk[c * 512 + h * 64 + lane]      * q[h * 64 + lane]
            + Wk[c * 512 + h * 64 + lane + 32] * q[h * 64 + lane + 32];
#pragma unroll
    for (int m = 16; m; m >>= 1) a += __shfl_xor_sync(0xffffffffu, a, m);
    if (lane == 0) g_wqT[h * C_ + c] = a * LOG2E;
}

// ---------------- Kernel B: warp-specialized fused softmax-pool + fused combine --------
// 4 score warps (w0-3) + 4 acc warps (w4-7); 3 x 32-row bulk-copy ring (96KB).
// Producer = acc-warp-0 lane 0. Last CTA per batch (threadfence-reduction pattern)
// merges the batch's partials and does the Wv projection itself.
__global__ void __launch_bounds__(256, 2) mha_main(const float* __restrict__ kv,
                                                   const float* __restrict__ Wv,
                                                   const float* __restrict__ bv,
                                                   float* __restrict__ out) {
    extern __shared__ __align__(128) char dsm[];
    char* sm_rows = dsm;
    ull*  sm_w    = reinterpret_cast<ull*>(dsm + SMW_OFF);    // [slot][warp][pair][h]

    const int tid  = threadIdx.x;
    const int w    = tid >> 5;
    const int lane = tid & 31;
    const int b  = blockIdx.x / CHB;
    const int ch = blockIdx.x % CHB;
    const int gstart = (ch * GROUPS_PER_B) / CHB;
    const int gend   = ((ch + 1) * GROUPS_PER_B) / CHB;
    const int ntiles = gend - gstart;

    const uint32_t mb_full = smem_u32(dsm + MBAR_OFF);
    const uint32_t mb_ws   = mb_full + NSTAGE * 8u;
    const uint32_t mb_emp  = mb_full + 2u * NSTAGE * 8u;
    const uint32_t rows_u32 = smem_u32(sm_rows);

    if (tid == 0) {
#pragma unroll
        for (int s = 0; s < NSTAGE; s++) {
            MBARRIER_INIT(mb_full + 8u * s, 1);
            MBARRIER_INIT(mb_ws   + 8u * s, 128);
            MBARRIER_INIT(mb_emp  + 8u * s, 128);
        }
    }
    __syncthreads();

    const float* src = kv + ((size_t)b * S_ + (size_t)gstart * STAGE_ROWS) * C_;
    float* dst = g_part + (size_t)blockIdx.x * PART_STRIDE;

    // prologue: PREFETCH stages in flight (issued by acc-warp-0 lane 0)
    if (tid == 128) {
#pragma unroll
        for (int u = 0; u < PREFETCH; u++) {
            MBARRIER_EXPECT_TX(mb_full + 8u * u, STAGE_BYTES);
            BULK_G2S(rows_u32 + u * STAGE_BYTES, src + (size_t)u * STAGE_ROWS * C_,
                     STAGE_BYTES, mb_full + 8u * u);
        }
    }

    if (w < 4) {
        // ================= score warps =================
        ull wq2[4][NH_];
#pragma unroll
        for (int j2 = 0; j2 < 4; j2++) {
            const int cbase = (j2 < 2) ? (4 * lane + 2 * j2) : (128 + 4 * lane + 2 * (j2 - 2));
#pragma unroll
            for (int h = 0; h < NH_; h++)
                wq2[j2][h] = *reinterpret_cast<const ull*>(g_wqT + h * C_ + cbase);
        }

        ull sum2 = 0ull;
        int slot = 0, par = 0;
        for (int t = 0; t < ntiles; t++) {
            MBARRIER_WAIT_PARITY(mb_full + 8u * slot, par);
            const char* rbase = sm_rows + slot * STAGE_BYTES;

            // Two pair-groups; within each, the two reduce chains interleave
            // (independent -> 26-cyc shfl latencies mutually hide). Feasible
            // now that acc2 is scoped out of this branch (regs ~120 < 128).
#pragma unroll
            for (int pp = 0; pp < 2; pp++) {
                ull v0[8], v1[8];
                score_pair(rbase, 8 * w + 4 * pp,     lane, wq2, v0);
                score_pair(rbase, 8 * w + 4 * pp + 2, lane, wq2, v1);
                red_l16(v0, lane);  red_l16(v1, lane);
                red_l8(v0, lane);   red_l8(v1, lane);
                red_l4(v0, lane);   red_l4(v1, lane);
                v0[0] = f2add(v0[0], shx64(v0[0], 2));
                v1[0] = f2add(v1[0], shx64(v1[0], 2));
                v0[0] = f2add(v0[0], shx64(v0[0], 1));
                v1[0] = f2add(v1[0], shx64(v1[0], 1));

                float2 e0 = upk(v0[0]), e1 = upk(v1[0]);
                asm("ex2.approx.f32 %0, %0;" : "+f"(e0.x));
                asm("ex2.approx.f32 %0, %0;" : "+f"(e0.y));
                asm("ex2.approx.f32 %0, %0;" : "+f"(e1.x));
                asm("ex2.approx.f32 %0, %0;" : "+f"(e1.y));
                ull w0 = pk(e0.x, e0.y), w1 = pk(e1.x, e1.y);
                sum2 = f2add(sum2, f2add(w0, w1));

                if ((lane & 3) == 0) {
                    sm_w[((slot * 4 + w) * 4 + 2 * pp)     * NH_ + (lane >> 2)] = w0;
                    sm_w[((slot * 4 + w) * 4 + 2 * pp + 1) * NH_ + (lane >> 2)] = w1;
                }
            }
            MBARRIER_ARRIVE(mb_ws + 8u * slot);
            if (++slot == NSTAGE) { slot = 0; par ^= 1; }
        }
        // per-warp head sums straight to gmem (combine sums the 4 warps)
        if ((lane & 3) == 0) {
            float2 sv = upk(sum2);
            dst[2048 + w * NH_ + (lane >> 2)] = sv.x + sv.y;
        }
    } else {
        // ============ acc warps (warp 4 lane 0 doubles as producer) ============
        const int wa = w - 4;
        ull acc2[NH_][4];
#pragma unroll
        for (int h = 0; h < NH_; h++)
#pragma unroll
            for (int j2 = 0; j2 < 4; j2++) acc2[h][j2] = 0ull;

        int slot = 0, par = 0;
        int uslot = PREFETCH, upar = 0;
        for (int t = 0; t < ntiles; t++) {
            if (tid == 128) {
                const int u = t + PREFETCH;
                if (u < ntiles) {
                    if (u >= NSTAGE) MBARRIER_WAIT_PARITY_RELAXED(mb_emp + 8u * uslot, upar ^ 1);
                    MBARRIER_EXPECT_TX(mb_full + 8u * uslot, STAGE_BYTES);
                    BULK_G2S(rows_u32 + uslot * STAGE_BYTES, src + (size_t)u * STAGE_ROWS * C_,
                             STAGE_BYTES, mb_full + 8u * uslot);
                    if (++uslot == NSTAGE) { uslot = 0; upar ^= 1; }
                }
            }
            MBARRIER_WAIT_PARITY(mb_ws + 8u * slot, par);
            const char* rbase = sm_rows + slot * STAGE_BYTES;

#pragma unroll
            for (int pair = 0; pair < 4; pair++) {
                const int r0 = 8 * wa + 2 * pair;
                ull kv0[4], kv1[4];
                load_row(kv0, rbase + r0 * 1024, lane);
                load_row(kv1, rbase + (r0 + 1) * 1024, lane);
#pragma unroll
                for (int h = 0; h < NH_; h++) {
                    ull wll = sm_w[((slot * 4 + wa) * 4 + pair) * NH_ + h];
                    float2 e = upk(wll);
                    ull a0 = pk(e.x, e.x), a1 = pk(e.y, e.y);
#pragma unroll
                    for (int j2 = 0; j2 < 4; j2++)
                        acc2[h][j2] = f2fma(a0, kv0[j2], f2fma(a1, kv1[j2], acc2[h][j2]));
                }
            }
            MBARRIER_ARRIVE(mb_emp + 8u * slot);
            if (++slot == NSTAGE) { slot = 0; par ^= 1; }
        }

        // ---- acc-warps-only merge (score warps finished all slot reads earlier) ----
        asm volatile("bar.sync 1, 128;" ::: "memory");
        float* red = reinterpret_cast<float*>(sm_rows);   // [4][2048], absolute-c layout
#pragma unroll
        for (int h = 0; h < NH_; h++) {
            *reinterpret_cast<ull*>(&red[wa * 2048 + h * C_ + 4 * lane])           = acc2[h][0];
            *reinterpret_cast<ull*>(&red[wa * 2048 + h * C_ + 4 * lane + 2])       = acc2[h][1];
            *reinterpret_cast<ull*>(&red[wa * 2048 + h * C_ + 128 + 4 * lane])     = acc2[h][2];
            *reinterpret_cast<ull*>(&red[wa * 2048 + h * C_ + 128 + 4 * lane + 2]) = acc2[h][3];
        }
        asm volatile("bar.sync 1, 128;" ::: "memory");

        const int at = wa * 32 + lane;   // 0..127, each merges 16 floats
#pragma unroll
        for (int j = 0; j < 8; j++) {
            ull a = *reinterpret_cast<ull*>(&red[at * 16 + 2 * j]);
            a = f2add(a, *reinterpret_cast<ull*>(&red[2048 + at * 16 + 2 * j]));
            a = f2add(a, *reinterpret_cast<ull*>(&red[4096 + at * 16 + 2 * j]));
            a = f2add(a, *reinterpret_cast<ull*>(&red[6144 + at * 16 + 2 * j]));
            *reinterpret_cast<ull*>(dst + at * 16 + 2 * j) = a;
        }
    }

    // ================= last-CTA-per-batch fused combine =================
    __syncthreads();                     // all g_part writes by this CTA issued
    __shared__ int s_win;
    if (tid == 0) {
        __threadfence();                 // release this CTA's g_part writes
        int old = atomicAdd(&g_done[b], 1);
        s_win = (old == CHB - 1);
        if (s_win) g_done[b] = 0;        // reset for next graph replay
    }
    __syncthreads();
    if (!s_win) return;
    __threadfence();                     // acquire other CTAs' g_part writes

    const size_t bbase = (size_t)b * CHB * PART_STRIDE;
    float* smf   = reinterpret_cast<float*>(dsm);   // smem reuse (post-sync)
    float* m_s   = smf;                             // 256
    float* gaccs = smf + 256;                       // 4*64
    float* s_all = smf + 512;                       // CHB*32 = 576
    __shared__ float sS[NH_];

    for (int i = tid; i < CHB * 32; i += 256)
        s_all[i] = g_part[bbase + (size_t)(i >> 5) * PART_STRIDE + 2048 + (i & 31)];
    __syncthreads();
    if (tid < NH_) {
        float S = 0.f;
#pragma unroll
        for (int k = 0; k < CHB; k++)
#pragma unroll
            for (int w2 = 0; w2 < 4; w2++) S += s_all[k * 32 + w2 * NH_ + tid];
        sS[tid] = S;
    }
    __syncthreads();

    const int qq = tid >> 6, vd = tid & 63;
#pragma unroll
    for (int h = 0; h < NH_; h++) {
        float M = 0.f;
#pragma unroll
        for (int k = 0; k < CHB; k++)
            M += g_part[bbase + (size_t)k * PART_STRIDE + h * C_ + tid];
        m_s[tid] = M;
        __syncthreads();
        float acc = 0.f;
#pragma unroll 8
        for (int i = 0; i < 64; i++) {
            int c = qq * 64 + i;
            acc += m_s[c] * Wv[c * (NH_ * VD_) + h * VD_ + vd];
        }
        gaccs[qq * 64 + vd] = acc;
        __syncthreads();
        if (tid < VD_)
            out[(b * NH_ + h) * VD_ + tid] =
                (gaccs[tid] + gaccs[64 + tid] + gaccs[128 + tid] + gaccs[192 + tid]) / sS[h]
                + bv[h * VD_ + tid];
        __syncthreads();   // m_s/gaccs rewritten next h
    }
}

extern "C" void kernel_launch(void* const* d_in, const int* in_sizes, int n_in,
                              void* d_out, int out_size) {
    const float* kv = (const float*)d_in[0];
    const float* Wk = (const float*)d_in[1];
    // d_in[2] = bk: per-(b,h) additive constant on scores -> cancels in softmax, unused.
    const float* Wv = (const float*)d_in[3];
    const float* bv = (const float*)d_in[4];
    const float* q  = (const float*)d_in[5];
    float* out = (float*)d_out;

    cudaFuncSetAttribute(mha_main, cudaFuncAttributeMaxDynamicSharedMemorySize, SMEM_TOTAL);

    mha_prep<<<128, 512>>>(Wk, q);
    mha_main<<<NCTA, 256, SMEM_TOTAL>>>(kv, Wv, bv, out);
}

// round 11
// speedup vs baseline: 1.0936x; 1.0936x over previous
#include <cuda_runtime.h>
#include <cstdint>

typedef unsigned long long ull;

#define B_ 16
#define S_ 16384
#define C_ 256
#define NH_ 8
#define VD_ 64
#define CHB 18                            /* chunks per batch */
#define NCTA (B_ * CHB)                   /* 288 = 2 CTAs per SM, one wave */
#define PART_STRIDE 2080                  /* 2048 acc + 4 groups x 8 head-sums */
#define GROUPS_PER_B 512                  /* 32-row groups per batch */
#define NSTAGE 3
#define PREFETCH 2
#define STAGE_ROWS 32
#define STAGE_BYTES (STAGE_ROWS * C_ * 4) /* 32768 */
#define LOG2E 1.4426950408889634f

/* dynamic smem layout */
#define MBAR_OFF (NSTAGE * STAGE_BYTES)               /* 98304: 6 mbarriers */
#define SMEM_TOTAL (MBAR_OFF + 128)                   /* 98432 */

// Device-global scratch (no runtime allocation allowed).
__device__ __align__(16) float g_wqT[NH_ * C_];                  // (Wk @ q) * log2e, [h][c]
__device__ __align__(16) float g_part[(size_t)NCTA * PART_STRIDE];

// ---------------- packed f32x2 helpers ----------------
__device__ __forceinline__ ull f2fma(ull a, ull b, ull c) {
    ull d; asm("fma.rn.f32x2 %0,%1,%2,%3;" : "=l"(d) : "l"(a), "l"(b), "l"(c)); return d;
}
__device__ __forceinline__ ull f2mul(ull a, ull b) {
    ull d; asm("mul.rn.f32x2 %0,%1,%2;" : "=l"(d) : "l"(a), "l"(b)); return d;
}
__device__ __forceinline__ ull f2add(ull a, ull b) {
    ull d; asm("add.rn.f32x2 %0,%1,%2;" : "=l"(d) : "l"(a), "l"(b)); return d;
}
__device__ __forceinline__ ull pk(float x, float y) {
    ull r; asm("mov.b64 %0,{%1,%2};" : "=l"(r) : "f"(x), "f"(y)); return r;
}
__device__ __forceinline__ float2 upk(ull v) {
    float2 r; asm("mov.b64 {%0,%1},%2;" : "=f"(r.x), "=f"(r.y) : "l"(v)); return r;
}
__device__ __forceinline__ ull shx64(ull v, int m) {
    unsigned lo, hi;
    asm("mov.b64 {%0,%1},%2;" : "=r"(lo), "=r"(hi) : "l"(v));
    lo = __shfl_xor_sync(0xffffffffu, lo, m);
    hi = __shfl_xor_sync(0xffffffffu, hi, m);
    ull r; asm("mov.b64 %0,{%1,%2};" : "=l"(r) : "r"(lo), "r"(hi)); return r;
}
__device__ __forceinline__ ull shidx64(ull v, int src) {
    unsigned lo, hi;
    asm("mov.b64 {%0,%1},%2;" : "=r"(lo), "=r"(hi) : "l"(v));
    lo = __shfl_sync(0xffffffffu, lo, src);
    hi = __shfl_sync(0xffffffffu, hi, src);
    ull r; asm("mov.b64 %0,{%1,%2};" : "=l"(r) : "r"(lo), "r"(hi)); return r;
}

__device__ __forceinline__ uint32_t smem_u32(const void* p) {
    uint32_t a;
    asm("{ .reg .u64 t; cvta.to.shared.u64 t, %1; cvt.u32.u64 %0, t; }" : "=r"(a) : "l"(p));
    return a;
}

// ---------------- mbarrier / bulk-copy primitives ----------------
#define MBARRIER_INIT(mbar, cnt) \
    asm volatile("mbarrier.init.shared.b64 [%0], %1;" :: "r"(mbar), "r"((uint32_t)(cnt)) : "memory")
#define MBARRIER_ARRIVE(mbar) \
    asm volatile("mbarrier.arrive.shared.b64 _, [%0];" :: "r"(mbar) : "memory")
#define MBARRIER_EXPECT_TX(mbar, bytes) \
    asm volatile("mbarrier.arrive.expect_tx.shared.b64 _, [%0], %1;" :: "r"(mbar), "r"((uint32_t)(bytes)) : "memory")

#define MBARRIER_WAIT_PARITY(mbar, par) do {                                            \
    uint32_t _m = (mbar), _p = (uint32_t)(par), _done;                                  \
    asm volatile("{\n\t.reg .pred p;\n\t"                                               \
        "mbarrier.try_wait.parity.acquire.cta.shared::cta.b64 p, [%1], %2;\n\t"         \
        "selp.b32 %0, 1, 0, p;\n\t}"                                                    \
        : "=r"(_done) : "r"(_m), "r"(_p) : "memory");                                   \
    if (!_done) {                                                                       \
        asm volatile("{\n\t.reg .pred P1;\n\t"                                          \
            "WL_%=:\n\t"                                                                \
            "mbarrier.try_wait.parity.acquire.cta.shared::cta.b64 P1, [%0], %1, 0x989680;\n\t" \
            "@P1 bra.uni WD_%=;\n\t"                                                    \
            "bra.uni WL_%=;\n\t"                                                        \
            "WD_%=:\n\t}"                                                               \
            :: "r"(_m), "r"(_p) : "memory");                                            \
    }                                                                                   \
} while (0)

#define MBARRIER_WAIT_PARITY_RELAXED(mbar, par) do {                                    \
    uint32_t _m = (mbar), _p = (uint32_t)(par), _done;                                  \
    asm volatile("{\n\t.reg .pred p;\n\t"                                               \
        "mbarrier.try_wait.parity.relaxed.cta.shared::cta.b64 p, [%1], %2, 0x989680;\n\t" \
        "selp.b32 %0, 1, 0, p;\n\t}"                                                    \
        : "=r"(_done) : "r"(_m), "r"(_p) : "memory");                                   \
    if (!_done) {                                                                       \
        asm volatile("{\n\t.reg .pred P1;\n\t"                                          \
            "WL_%=:\n\t"                                                                \
            "mbarrier.try_wait.parity.relaxed.cta.shared::cta.b64 P1, [%0], %1, 0x989680;\n\t" \
            "@P1 bra.uni WD_%=;\n\t"                                                    \
            "bra.uni WL_%=;\n\t"                                                        \
            "WD_%=:\n\t}"                                                               \
            :: "r"(_m), "r"(_p) : "memory");                                            \
    }                                                                                   \
} while (0)

#define BULK_G2S(dst_u32, src_ptr, bytes, mbar) \
    asm volatile("cp.async.bulk.shared::cluster.global.mbarrier::complete_tx::bytes [%0], [%1], %2, [%3];" \
        :: "r"(dst_u32), "l"(src_ptr), "r"((uint32_t)(bytes)), "r"(mbar) : "memory")

// Conflict-free 2-row load: lane owns c in {4l..4l+3} and {128+4l..128+4l+3}.
__device__ __forceinline__ void load_row(ull out[4], const char* rowp, int lane) {
    ulonglong2 a0 = *reinterpret_cast<const ulonglong2*>(rowp + lane * 16);
    ulonglong2 a1 = *reinterpret_cast<const ulonglong2*>(rowp + 512 + lane * 16);
    out[0] = a0.x; out[1] = a0.y; out[2] = a1.x; out[3] = a1.y;
}

// Value-halving reduction of 4 packed values over 32 lanes.
// Afterwards EVERY lane holds the full-warp sum of value index (lane>>3)&3.
__device__ __forceinline__ ull reduce4(ull v[4], int lane) {
    {
        bool hi = (lane & 16) != 0;
#pragma unroll
        for (int j = 0; j < 2; j++) {
            ull snd = hi ? v[j] : v[j + 2];
            ull kp  = hi ? v[j + 2] : v[j];
            v[j] = f2add(kp, shx64(snd, 16));
        }
    }
    {
        bool hi = (lane & 8) != 0;
        ull snd = hi ? v[0] : v[1];
        ull kp  = hi ? v[1] : v[0];
        v[0] = f2add(kp, shx64(snd, 8));
    }
    v[0] = f2add(v[0], shx64(v[0], 4));
    v[0] = f2add(v[0], shx64(v[0], 2));
    v[0] = f2add(v[0], shx64(v[0], 1));
    return v[0];
}

// ---------------- Kernel A: fold Wk @ q -> wq[h][c], scaled by log2e ----------------
__global__ void mha_prep(const float* __restrict__ Wk, const float* __restrict__ q) {
    int w = threadIdx.x >> 5, lane = threadIdx.x & 31;
    int idx = blockIdx.x * 16 + w;   // 0..2047 = h*256 + c
    int h = idx >> 8, c = idx & 255;
    float a = Wk[c * 512 + h * 64 + lane]      * q[h * 64 + lane]
            + Wk[c * 512 + h * 64 + lane + 32] * q[h * 64 + lane + 32];
#pragma unroll
    for (int m = 16; m; m >>= 1) a += __shfl_xor_sync(0xffffffffu, a, m);
    if (lane == 0) g_wqT[h * C_ + c] = a * LOG2E;
}

// ---------------- Kernel B: symmetric head-split fused softmax-pool ----------------
// 8 identical warps. Warp w = 2g+hs owns rows [8g,8g+8) and heads [4hs,4hs+4):
// it scores AND accumulates its own block -> no score->acc barrier, weights
// stay in registers. 3 x 32-row bulk-copy ring; producer = warp 0 lane 0.
__global__ void __launch_bounds__(256, 2) mha_main(const float* __restrict__ kv) {
    extern __shared__ __align__(128) char dsm[];
    char* sm_rows = dsm;

    const int tid  = threadIdx.x;
    const int w    = tid >> 5;
    const int lane = tid & 31;
    const int g    = w >> 1;          // row group 0..3 (8 rows each)
    const int hb   = (w & 1) * 4;     // head base: 0 or 4
    const int b  = blockIdx.x / CHB;
    const int ch = blockIdx.x % CHB;
    const int gstart = (ch * GROUPS_PER_B) / CHB;
    const int gend   = ((ch + 1) * GROUPS_PER_B) / CHB;
    const int ntiles = gend - gstart;

    const uint32_t mb_full = smem_u32(dsm + MBAR_OFF);
    const uint32_t mb_emp  = mb_full + NSTAGE * 8u;
    const uint32_t rows_u32 = smem_u32(sm_rows);

    if (tid == 0) {
#pragma unroll
        for (int s = 0; s < NSTAGE; s++) {
            MBARRIER_INIT(mb_full + 8u * s, 1);
            MBARRIER_INIT(mb_emp  + 8u * s, 8);   // one arrive per warp
        }
    }
    __syncthreads();

    const float* src = kv + ((size_t)b * S_ + (size_t)gstart * STAGE_ROWS) * C_;
    float* dst = g_part + (size_t)blockIdx.x * PART_STRIDE;

    // prologue: PREFETCH stages in flight
    if (tid == 0) {
#pragma unroll
        for (int u = 0; u < PREFETCH; u++) {
            MBARRIER_EXPECT_TX(mb_full + 8u * u, STAGE_BYTES);
            BULK_G2S(rows_u32 + u * STAGE_BYTES, src + (size_t)u * STAGE_ROWS * C_,
                     STAGE_BYTES, mb_full + 8u * u);
        }
    }

    // loop-invariant packed query-weights for this warp's 4 heads
    ull wq2[4][4];   // [j2][i], head hb+i
#pragma unroll
    for (int j2 = 0; j2 < 4; j2++) {
        const int cbase = (j2 < 2) ? (4 * lane + 2 * j2) : (128 + 4 * lane + 2 * (j2 - 2));
#pragma unroll
        for (int i = 0; i < 4; i++)
            wq2[j2][i] = *reinterpret_cast<const ull*>(g_wqT + (hb + i) * C_ + cbase);
    }

    ull acc2[4][4];  // [head i][j2]
#pragma unroll
    for (int i = 0; i < 4; i++)
#pragma unroll
        for (int j2 = 0; j2 < 4; j2++) acc2[i][j2] = 0ull;
    ull sum2 = 0ull;  // per-lane: head hb + ((lane>>3)&3)

    int slot = 0, par = 0;
    int uslot = PREFETCH, upar = 0;
    for (int t = 0; t < ntiles; t++) {
        if (tid == 0) {
            const int u = t + PREFETCH;
            if (u < ntiles) {
                if (u >= NSTAGE) MBARRIER_WAIT_PARITY_RELAXED(mb_emp + 8u * uslot, upar ^ 1);
                MBARRIER_EXPECT_TX(mb_full + 8u * uslot, STAGE_BYTES);
                BULK_G2S(rows_u32 + uslot * STAGE_BYTES, src + (size_t)u * STAGE_ROWS * C_,
                         STAGE_BYTES, mb_full + 8u * uslot);
                if (++uslot == NSTAGE) { uslot = 0; upar ^= 1; }
            }
        }
        MBARRIER_WAIT_PARITY(mb_full + 8u * slot, par);
        const char* rbase = sm_rows + slot * STAGE_BYTES;

#pragma unroll
        for (int pair = 0; pair < 4; pair++) {
            const int r0 = 8 * g + 2 * pair;
            ull kv0[4], kv1[4];
            load_row(kv0, rbase + r0 * 1024, lane);
            load_row(kv1, rbase + (r0 + 1) * 1024, lane);

            // scores for 4 heads x 2 rows
            ull v[4];
            {
                float s0[4];
                ull p[4];
#pragma unroll
                for (int i = 0; i < 4; i++) p[i] = f2mul(kv0[0], wq2[0][i]);
#pragma unroll
                for (int j2 = 1; j2 < 4; j2++)
#pragma unroll
                    for (int i = 0; i < 4; i++) p[i] = f2fma(kv0[j2], wq2[j2][i], p[i]);
#pragma unroll
                for (int i = 0; i < 4; i++) { float2 u2 = upk(p[i]); s0[i] = u2.x + u2.y; }
#pragma unroll
                for (int i = 0; i < 4; i++) p[i] = f2mul(kv1[0], wq2[0][i]);
#pragma unroll
                for (int j2 = 1; j2 < 4; j2++)
#pragma unroll
                    for (int i = 0; i < 4; i++) p[i] = f2fma(kv1[j2], wq2[j2][i], p[i]);
#pragma unroll
                for (int i = 0; i < 4; i++) { float2 u2 = upk(p[i]); v[i] = pk(s0[i], u2.x + u2.y); }
            }

            ull r = reduce4(v, lane);   // every lane: sum for head hb+((lane>>3)&3)
            float2 e = upk(r);
            asm("ex2.approx.f32 %0, %0;" : "+f"(e.x));
            asm("ex2.approx.f32 %0, %0;" : "+f"(e.y));
            ull wgt = pk(e.x, e.y);
            sum2 = f2add(sum2, wgt);

            // accumulate this warp's 4 heads with its own weights (register-resident)
#pragma unroll
            for (int i = 0; i < 4; i++) {
                ull wi = shidx64(wgt, i * 8);
                float2 ei = upk(wi);
                ull a0 = pk(ei.x, ei.x), a1 = pk(ei.y, ei.y);
#pragma unroll
                for (int j2 = 0; j2 < 4; j2++)
                    acc2[i][j2] = f2fma(a0, kv0[j2], f2fma(a1, kv1[j2], acc2[i][j2]));
            }
        }

        __syncwarp();
        if (lane == 0) MBARRIER_ARRIVE(mb_emp + 8u * slot);
        if (++slot == NSTAGE) { slot = 0; par ^= 1; }
    }

    // per-(group,head) weight sums -> gmem (combine sums groups)
    if ((lane & 7) == 0) {
        float2 sv = upk(sum2);
        dst[2048 + g * 8 + hb + (lane >> 3)] = sv.x + sv.y;
    }

    // ---- CTA merge: 4 row-groups -> one partial ----
    __syncthreads();   // pipeline drained; stage smem reusable as merge area
    float* red = reinterpret_cast<float*>(sm_rows);   // [4 groups][2048], absolute-c layout
#pragma unroll
    for (int i = 0; i < 4; i++) {
        const int h = hb + i;
        *reinterpret_cast<ull*>(&red[g * 2048 + h * C_ + 4 * lane])           = acc2[i][0];
        *reinterpret_cast<ull*>(&red[g * 2048 + h * C_ + 4 * lane + 2])       = acc2[i][1];
        *reinterpret_cast<ull*>(&red[g * 2048 + h * C_ + 128 + 4 * lane])     = acc2[i][2];
        *reinterpret_cast<ull*>(&red[g * 2048 + h * C_ + 128 + 4 * lane + 2]) = acc2[i][3];
    }
    __syncthreads();

#pragma unroll
    for (int j = 0; j < 4; j++) {
        ull a = *reinterpret_cast<ull*>(&red[tid * 8 + 2 * j]);
        a = f2add(a, *reinterpret_cast<ull*>(&red[2048 + tid * 8 + 2 * j]));
        a = f2add(a, *reinterpret_cast<ull*>(&red[4096 + tid * 8 + 2 * j]));
        a = f2add(a, *reinterpret_cast<ull*>(&red[6144 + tid * 8 + 2 * j]));
        *reinterpret_cast<ull*>(dst + tid * 8 + 2 * j) = a;
    }
}

// ---------------- Kernel C: merge partials, normalize, project with Wv ----------------
__global__ void mha_combine(const float* __restrict__ Wv, const float* __restrict__ bv,
                            float* __restrict__ out) {
    const int b = blockIdx.x >> 3;
    const int h = blockIdx.x & 7;
    const int t = threadIdx.x;   // 256 threads

    __shared__ float m_s[C_];
    __shared__ float s_s[CHB * 4];
    __shared__ float gacc[4][VD_];

    const size_t base = (size_t)b * CHB * PART_STRIDE;
    float M = 0.f;
#pragma unroll
    for (int k = 0; k < CHB; k++)
        M += g_part[base + (size_t)k * PART_STRIDE + h * C_ + t];

    if (t < CHB * 4)
        s_s[t] = g_part[base + (size_t)(t >> 2) * PART_STRIDE + 2048 + (t & 3) * NH_ + h];
    __syncthreads();

    float S = 0.f;
#pragma unroll
    for (int k = 0; k < CHB * 4; k++) S += s_s[k];

    m_s[t] = M;   // unnormalized; divide once at the end
    __syncthreads();

    const int q  = t >> 6;    // c-quarter 0..3
    const int vd = t & 63;    // output dim
    float acc = 0.f;
#pragma unroll 8
    for (int i = 0; i < 64; i++) {
        int c = q * 64 + i;
        acc += m_s[c] * Wv[c * (NH_ * VD_) + h * VD_ + vd];   // coalesced across vd
    }
    gacc[q][vd] = acc;
    __syncthreads();

    if (t < VD_) {
        float r = (gacc[0][t] + gacc[1][t] + gacc[2][t] + gacc[3][t]) / S + bv[h * VD_ + t];
        out[(b * NH_ + h) * VD_ + t] = r;
    }
}

extern "C" void kernel_launch(void* const* d_in, const int* in_sizes, int n_in,
                              void* d_out, int out_size) {
    const float* kv = (const float*)d_in[0];
    const float* Wk = (const float*)d_in[1];
    // d_in[2] = bk: per-(b,h) additive constant on scores -> cancels in softmax, unused.
    const float* Wv = (const float*)d_in[3];
    const float* bv = (const float*)d_in[4];
    const float* q  = (const float*)d_in[5];
    float* out = (float*)d_out;

    cudaFuncSetAttribute(mha_main, cudaFuncAttributeMaxDynamicSharedMemorySize, SMEM_TOTAL);

    mha_prep<<<128, 512>>>(Wk, q);
    mha_main<<<NCTA, 256, SMEM_TOTAL>>>(kv);
    mha_combine<<<B_ * NH_, 256>>>(Wv, bv, out);
}

// round 12
// speedup vs baseline: 1.1409x; 1.0432x over previous
#include <cuda_runtime.h>
#include <cstdint>

typedef unsigned long long ull;

#define B_ 16
#define S_ 16384
#define C_ 256
#define NH_ 8
#define VD_ 64
#define CHB 18                            /* chunks per batch */
#define NCTA (B_ * CHB)                   /* 288 = 2 CTAs per SM, one wave */
#define PART_STRIDE 2080                  /* 2048 acc + 4 warps x 8 sums */
#define GROUPS_PER_B 512                  /* 32-row groups per batch */
#define NSTAGE 3
#define PREFETCH 2
#define STAGE_ROWS 32
#define STAGE_BYTES (STAGE_ROWS * C_ * 4) /* 32768 */
#define LOG2E 1.4426950408889634f

/* dynamic smem layout */
#define SMW_OFF  (NSTAGE * STAGE_BYTES)               /* 98304: weights 3*4*4*8 ull = 3072B */
#define MBAR_OFF (SMW_OFF + 3072)                     /* 101376: 9 mbarriers */
#define SMEM_TOTAL (MBAR_OFF + 128)                   /* 101504 */

// Device-global scratch (no runtime allocation allowed).
__device__ __align__(16) float g_wqT[NH_ * C_];                  // (Wk @ q) * log2e, [h][c]
__device__ __align__(16) float g_part[(size_t)NCTA * PART_STRIDE];
__device__ int g_done[B_];   // zero-init at module load; winner CTA resets -> replay-safe

// ---------------- packed f32x2 helpers ----------------
__device__ __forceinline__ ull f2fma(ull a, ull b, ull c) {
    ull d; asm("fma.rn.f32x2 %0,%1,%2,%3;" : "=l"(d) : "l"(a), "l"(b), "l"(c)); return d;
}
__device__ __forceinline__ ull f2mul(ull a, ull b) {
    ull d; asm("mul.rn.f32x2 %0,%1,%2;" : "=l"(d) : "l"(a), "l"(b)); return d;
}
__device__ __forceinline__ ull f2add(ull a, ull b) {
    ull d; asm("add.rn.f32x2 %0,%1,%2;" : "=l"(d) : "l"(a), "l"(b)); return d;
}
__device__ __forceinline__ ull pk(float x, float y) {
    ull r; asm("mov.b64 %0,{%1,%2};" : "=l"(r) : "f"(x), "f"(y)); return r;
}
__device__ __forceinline__ float2 upk(ull v) {
    float2 r; asm("mov.b64 {%0,%1},%2;" : "=f"(r.x), "=f"(r.y) : "l"(v)); return r;
}
__device__ __forceinline__ ull shx64(ull v, int m) {
    unsigned lo, hi;
    asm("mov.b64 {%0,%1},%2;" : "=r"(lo), "=r"(hi) : "l"(v));
    lo = __shfl_xor_sync(0xffffffffu, lo, m);
    hi = __shfl_xor_sync(0xffffffffu, hi, m);
    ull r; asm("mov.b64 %0,{%1,%2};" : "=l"(r) : "r"(lo), "r"(hi)); return r;
}

__device__ __forceinline__ uint32_t smem_u32(const void* p) {
    uint32_t a;
    asm("{ .reg .u64 t; cvta.to.shared.u64 t, %1; cvt.u32.u64 %0, t; }" : "=r"(a) : "l"(p));
    return a;
}

// ---------------- mbarrier / bulk-copy primitives ----------------
#define MBARRIER_INIT(mbar, cnt) \
    asm volatile("mbarrier.init.shared.b64 [%0], %1;" :: "r"(mbar), "r"((uint32_t)(cnt)) : "memory")
#define MBARRIER_ARRIVE(mbar) \
    asm volatile("mbarrier.arrive.shared.b64 _, [%0];" :: "r"(mbar) : "memory")
#define MBARRIER_EXPECT_TX(mbar, bytes) \
    asm volatile("mbarrier.arrive.expect_tx.shared.b64 _, [%0], %1;" :: "r"(mbar), "r"((uint32_t)(bytes)) : "memory")

#define MBARRIER_WAIT_PARITY(mbar, par) do {                                            \
    uint32_t _m = (mbar), _p = (uint32_t)(par), _done;                                  \
    asm volatile("{\n\t.reg .pred p;\n\t"                                               \
        "mbarrier.try_wait.parity.acquire.cta.shared::cta.b64 p, [%1], %2;\n\t"         \
        "selp.b32 %0, 1, 0, p;\n\t}"                                                    \
        : "=r"(_done) : "r"(_m), "r"(_p) : "memory");                                   \
    if (!_done) {                                                                       \
        asm volatile("{\n\t.reg .pred P1;\n\t"                                          \
            "WL_%=:\n\t"                                                                \
            "mbarrier.try_wait.parity.acquire.cta.shared::cta.b64 P1, [%0], %1, 0x989680;\n\t" \
            "@P1 bra.uni WD_%=;\n\t"                                                    \
            "bra.uni WL_%=;\n\t"                                                        \
            "WD_%=:\n\t}"                                                               \
            :: "r"(_m), "r"(_p) : "memory");                                            \
    }                                                                                   \
} while (0)

#define MBARRIER_WAIT_PARITY_RELAXED(mbar, par) do {                                    \
    uint32_t _m = (mbar), _p = (uint32_t)(par), _done;                                  \
    asm volatile("{\n\t.reg .pred p;\n\t"                                               \
        "mbarrier.try_wait.parity.relaxed.cta.shared::cta.b64 p, [%1], %2, 0x989680;\n\t" \
        "selp.b32 %0, 1, 0, p;\n\t}"                                                    \
        : "=r"(_done) : "r"(_m), "r"(_p) : "memory");                                   \
    if (!_done) {                                                                       \
        asm volatile("{\n\t.reg .pred P1;\n\t"                                          \
            "WL_%=:\n\t"                                                                \
            "mbarrier.try_wait.parity.relaxed.cta.shared::cta.b64 P1, [%0], %1, 0x989680;\n\t" \
            "@P1 bra.uni WD_%=;\n\t"                                                    \
            "bra.uni WL_%=;\n\t"                                                        \
            "WD_%=:\n\t}"                                                               \
            :: "r"(_m), "r"(_p) : "memory");                                            \
    }                                                                                   \
} while (0)

#define BULK_G2S(dst_u32, src_ptr, bytes, mbar) \
    asm volatile("cp.async.bulk.shared::cluster.global.mbarrier::complete_tx::bytes [%0], [%1], %2, [%3];" \
        :: "r"(dst_u32), "l"(src_ptr), "r"((uint32_t)(bytes)), "r"(mbar) : "memory")

// Value-halving warp reduction: 8 packed f32x2 values summed over 32 lanes.
// Afterwards, lane l holds the full-warp sum of value index (l>>2)&7.
__device__ __forceinline__ ull reduce8(ull v[8], int lane) {
    {
        bool hi = (lane & 16) != 0;
#pragma unroll
        for (int j = 0; j < 4; j++) {
            ull snd = hi ? v[j] : v[j + 4];
            ull kp  = hi ? v[j + 4] : v[j];
            v[j] = f2add(kp, shx64(snd, 16));
        }
    }
    {
        bool hi = (lane & 8) != 0;
#pragma unroll
        for (int j = 0; j < 2; j++) {
            ull snd = hi ? v[j] : v[j + 2];
            ull kp  = hi ? v[j + 2] : v[j];
            v[j] = f2add(kp, shx64(snd, 8));
        }
    }
    {
        bool hi = (lane & 4) != 0;
        ull snd = hi ? v[0] : v[1];
        ull kp  = hi ? v[1] : v[0];
        v[0] = f2add(kp, shx64(snd, 4));
    }
    v[0] = f2add(v[0], shx64(v[0], 2));
    v[0] = f2add(v[0], shx64(v[0], 1));
    return v[0];
}

// Conflict-free 2-row load: lane owns c in {4l..4l+3} and {128+4l..128+4l+3}.
__device__ __forceinline__ void load_row(ull out[4], const char* rowp, int lane) {
    ulonglong2 a0 = *reinterpret_cast<const ulonglong2*>(rowp + lane * 16);
    ulonglong2 a1 = *reinterpret_cast<const ulonglong2*>(rowp + 512 + lane * 16);
    out[0] = a0.x; out[1] = a0.y; out[2] = a1.x; out[3] = a1.y;
}

// Score FMA for a 2-row pair -> packed v[8] (per-head, rows in f32x2 lanes).
__device__ __forceinline__ void score_pair(const char* rbase, int r0, int lane,
                                           const ull wq2[4][NH_], ull v[8]) {
    ull kv0[4], kv1[4];
    load_row(kv0, rbase + r0 * 1024, lane);
    load_row(kv1, rbase + (r0 + 1) * 1024, lane);
    float s0[NH_];
    ull p[NH_];
#pragma unroll
    for (int h = 0; h < NH_; h++) p[h] = f2mul(kv0[0], wq2[0][h]);
#pragma unroll
    for (int j2 = 1; j2 < 4; j2++)
#pragma unroll
        for (int h = 0; h < NH_; h++) p[h] = f2fma(kv0[j2], wq2[j2][h], p[h]);
#pragma unroll
    for (int h = 0; h < NH_; h++) { float2 u2 = upk(p[h]); s0[h] = u2.x + u2.y; }
#pragma unroll
    for (int h = 0; h < NH_; h++) p[h] = f2mul(kv1[0], wq2[0][h]);
#pragma unroll
    for (int j2 = 1; j2 < 4; j2++)
#pragma unroll
        for (int h = 0; h < NH_; h++) p[h] = f2fma(kv1[j2], wq2[j2][h], p[h]);
#pragma unroll
    for (int h = 0; h < NH_; h++) { float2 u2 = upk(p[h]); v[h] = pk(s0[h], u2.x + u2.y); }
}

// ---------------- Kernel A: fold Wk @ q -> wq[h][c], scaled by log2e ----------------
__global__ void mha_prep(const float* __restrict__ Wk, const float* __restrict__ q) {
    int w = threadIdx.x >> 5, lane = threadIdx.x & 31;
    int idx = blockIdx.x * 8 + w;    // 0..2047 = h*256 + c
    int h = idx >> 8, c = idx & 255;
    float a = Wk[c * 512 + h * 64 + lane]      * q[h * 64 + lane]
            + Wk[c * 512 + h * 64 + lane + 32] * q[h * 64 + lane + 32];
#pragma unroll
    for (int m = 16; m; m >>= 1) a += __shfl_xor_sync(0xffffffffu, a, m);
    if (lane == 0) g_wqT[h * C_ + c] = a * LOG2E;
}

// ---------------- Kernel B: warp-specialized fused softmax-pool + fused combine ----------
// 4 score warps (w0-3) + 4 acc warps (w4-7); 3 x 32-row bulk-copy ring (96KB).
// Producer = acc-warp-0 lane 0. Last CTA per batch merges partials and projects with Wv
// (warp-per-head, so the epilogue tail is short and parallel).
__global__ void __launch_bounds__(256, 2) mha_main(const float* __restrict__ kv,
                                                   const float* __restrict__ Wv,
                                                   const float* __restrict__ bv,
                                                   float* __restrict__ out) {
    extern __shared__ __align__(128) char dsm[];
    char* sm_rows = dsm;
    ull*  sm_w    = reinterpret_cast<ull*>(dsm + SMW_OFF);    // [slot][warp][pair][h]

    const int tid  = threadIdx.x;
    const int w    = tid >> 5;
    const int lane = tid & 31;
    const int b  = blockIdx.x / CHB;
    const int ch = blockIdx.x % CHB;
    const int gstart = (ch * GROUPS_PER_B) / CHB;
    const int gend   = ((ch + 1) * GROUPS_PER_B) / CHB;
    const int ntiles = gend - gstart;

    const uint32_t mb_full = smem_u32(dsm + MBAR_OFF);
    const uint32_t mb_ws   = mb_full + NSTAGE * 8u;
    const uint32_t mb_emp  = mb_full + 2u * NSTAGE * 8u;
    const uint32_t rows_u32 = smem_u32(sm_rows);

    if (tid == 0) {
#pragma unroll
        for (int s = 0; s < NSTAGE; s++) {
            MBARRIER_INIT(mb_full + 8u * s, 1);
            MBARRIER_INIT(mb_ws   + 8u * s, 128);
            MBARRIER_INIT(mb_emp  + 8u * s, 128);
        }
    }
    __syncthreads();

    const float* src = kv + ((size_t)b * S_ + (size_t)gstart * STAGE_ROWS) * C_;
    float* dst = g_part + (size_t)blockIdx.x * PART_STRIDE;

    // prologue: PREFETCH stages in flight (issued by acc-warp-0 lane 0)
    if (tid == 128) {
#pragma unroll
        for (int u = 0; u < PREFETCH; u++) {
            MBARRIER_EXPECT_TX(mb_full + 8u * u, STAGE_BYTES);
            BULK_G2S(rows_u32 + u * STAGE_BYTES, src + (size_t)u * STAGE_ROWS * C_,
                     STAGE_BYTES, mb_full + 8u * u);
        }
    }

    if (w < 4) {
        // ================= score warps =================
        ull wq2[4][NH_];
#pragma unroll
        for (int j2 = 0; j2 < 4; j2++) {
            const int cbase = (j2 < 2) ? (4 * lane + 2 * j2) : (128 + 4 * lane + 2 * (j2 - 2));
#pragma unroll
            for (int h = 0; h < NH_; h++)
                wq2[j2][h] = *reinterpret_cast<const ull*>(g_wqT + h * C_ + cbase);
        }

        ull sum2 = 0ull;
        int slot = 0, par = 0;
        for (int t = 0; t < ntiles; t++) {
            MBARRIER_WAIT_PARITY(mb_full + 8u * slot, par);
            const char* rbase = sm_rows + slot * STAGE_BYTES;

#pragma unroll
            for (int pair = 0; pair < 4; pair++) {
                ull v[8];
                score_pair(rbase, 8 * w + 2 * pair, lane, wq2, v);
                reduce8(v, lane);
                float2 e = upk(v[0]);
                asm("ex2.approx.f32 %0, %0;" : "+f"(e.x));
                asm("ex2.approx.f32 %0, %0;" : "+f"(e.y));
                ull wgt = pk(e.x, e.y);
                sum2 = f2add(sum2, wgt);
                if ((lane & 3) == 0)
                    sm_w[((slot * 4 + w) * 4 + pair) * NH_ + (lane >> 2)] = wgt;
            }
            MBARRIER_ARRIVE(mb_ws + 8u * slot);
            if (++slot == NSTAGE) { slot = 0; par ^= 1; }
        }
        // per-warp head sums straight to gmem (epilogue sums the 4 warps)
        if ((lane & 3) == 0) {
            float2 sv = upk(sum2);
            dst[2048 + w * NH_ + (lane >> 2)] = sv.x + sv.y;
        }
    } else {
        // ============ acc warps (warp 4 lane 0 doubles as producer) ============
        const int wa = w - 4;
        ull acc2[NH_][4];
#pragma unroll
        for (int h = 0; h < NH_; h++)
#pragma unroll
            for (int j2 = 0; j2 < 4; j2++) acc2[h][j2] = 0ull;

        int slot = 0, par = 0;
        int uslot = PREFETCH, upar = 0;
        for (int t = 0; t < ntiles; t++) {
            if (tid == 128) {
                const int u = t + PREFETCH;
                if (u < ntiles) {
                    if (u >= NSTAGE) MBARRIER_WAIT_PARITY_RELAXED(mb_emp + 8u * uslot, upar ^ 1);
                    MBARRIER_EXPECT_TX(mb_full + 8u * uslot, STAGE_BYTES);
                    BULK_G2S(rows_u32 + uslot * STAGE_BYTES, src + (size_t)u * STAGE_ROWS * C_,
                             STAGE_BYTES, mb_full + 8u * uslot);
                    if (++uslot == NSTAGE) { uslot = 0; upar ^= 1; }
                }
            }
            MBARRIER_WAIT_PARITY(mb_ws + 8u * slot, par);
            const char* rbase = sm_rows + slot * STAGE_BYTES;

#pragma unroll
            for (int pair = 0; pair < 4; pair++) {
                const int r0 = 8 * wa + 2 * pair;
                ull kv0[4], kv1[4];
                load_row(kv0, rbase + r0 * 1024, lane);
                load_row(kv1, rbase + (r0 + 1) * 1024, lane);
#pragma unroll
                for (int h = 0; h < NH_; h++) {
                    ull wll = sm_w[((slot * 4 + wa) * 4 + pair) * NH_ + h];
                    float2 e = upk(wll);
                    ull a0 = pk(e.x, e.x), a1 = pk(e.y, e.y);
#pragma unroll
                    for (int j2 = 0; j2 < 4; j2++)
                        acc2[h][j2] = f2fma(a0, kv0[j2], f2fma(a1, kv1[j2], acc2[h][j2]));
                }
            }
            MBARRIER_ARRIVE(mb_emp + 8u * slot);
            if (++slot == NSTAGE) { slot = 0; par ^= 1; }
        }

        // ---- acc-warps-only merge (score warps finished all slot reads earlier) ----
        asm volatile("bar.sync 1, 128;" ::: "memory");
        float* red = reinterpret_cast<float*>(sm_rows);   // [4][2048], absolute-c layout
#pragma unroll
        for (int h = 0; h < NH_; h++) {
            *reinterpret_cast<ull*>(&red[wa * 2048 + h * C_ + 4 * lane])           = acc2[h][0];
            *reinterpret_cast<ull*>(&red[wa * 2048 + h * C_ + 4 * lane + 2])       = acc2[h][1];
            *reinterpret_cast<ull*>(&red[wa * 2048 + h * C_ + 128 + 4 * lane])     = acc2[h][2];
            *reinterpret_cast<ull*>(&red[wa * 2048 + h * C_ + 128 + 4 * lane + 2]) = acc2[h][3];
        }
        asm volatile("bar.sync 1, 128;" ::: "memory");

        const int at = wa * 32 + lane;   // 0..127, each merges 16 floats
#pragma unroll
        for (int j = 0; j < 8; j++) {
            ull a = *reinterpret_cast<ull*>(&red[at * 16 + 2 * j]);
            a = f2add(a, *reinterpret_cast<ull*>(&red[2048 + at * 16 + 2 * j]));
            a = f2add(a, *reinterpret_cast<ull*>(&red[4096 + at * 16 + 2 * j]));
            a = f2add(a, *reinterpret_cast<ull*>(&red[6144 + at * 16 + 2 * j]));
            *reinterpret_cast<ull*>(dst + at * 16 + 2 * j) = a;
        }
    }

    // ================= last-CTA-per-batch fused combine =================
    __threadfence();                     // release this CTA's g_part writes
    __syncthreads();
    __shared__ int s_win;
    if (tid == 0) {
        int old = atomicAdd(&g_done[b], 1);
        s_win = (old == CHB - 1) ? 1 : 0;
        if (s_win) g_done[b] = 0;        // reset for next graph replay
    }
    __syncthreads();
    if (!s_win) return;
    __threadfence();                     // acquire other CTAs' g_part writes

    const size_t bbase = (size_t)b * CHB * PART_STRIDE;
    float* m_all = reinterpret_cast<float*>(dsm);   // [8][256] merged M (smem reuse, post-sync)
    __shared__ float sS[NH_];

    // merged M for all heads: linear index i = h*256 + c (matches g_part layout)
#pragma unroll
    for (int i = tid; i < 2048; i += 256) {
        float M = 0.f;
#pragma unroll
        for (int k = 0; k < CHB; k++)
            M += g_part[bbase + (size_t)k * PART_STRIDE + i];
        m_all[i] = M;
    }
    // weight sums per head
    if (tid < NH_) {
        float S = 0.f;
#pragma unroll
        for (int k = 0; k < CHB; k++)
#pragma unroll
            for (int j = 0; j < 4; j++)
                S += g_part[bbase + (size_t)k * PART_STRIDE + 2048 + j * NH_ + tid];
        sS[tid] = S;
    }
    __syncthreads();

    // warp-per-head GEMV: lane computes 2 output dims; 4-way split accumulators
    {
        const int h = w;             // 8 warps = 8 heads
        const int vd = 2 * lane;
        const float* mrow = m_all + h * C_;
        const float* wcol = Wv + h * VD_ + vd;
        float a0 = 0.f, a1 = 0.f, b0 = 0.f, b1 = 0.f;
#pragma unroll 4
        for (int c = 0; c < C_; c += 2) {
            float2 w0 = *reinterpret_cast<const float2*>(wcol + (size_t)c * (NH_ * VD_));
            float2 w1 = *reinterpret_cast<const float2*>(wcol + (size_t)(c + 1) * (NH_ * VD_));
            float m0 = mrow[c], m1 = mrow[c + 1];
            a0 += m0 * w0.x;  a1 += m0 * w0.y;
            b0 += m1 * w1.x;  b1 += m1 * w1.y;
        }
        const float invS = 1.0f / sS[h];
        out[((size_t)b * NH_ + h) * VD_ + vd]     = (a0 + b0) * invS + bv[h * VD_ + vd];
        out[((size_t)b * NH_ + h) * VD_ + vd + 1] = (a1 + b1) * invS + bv[h * VD_ + vd + 1];
    }
}

extern "C" void kernel_launch(void* const* d_in, const int* in_sizes, int n_in,
                              void* d_out, int out_size) {
    const float* kv = (const float*)d_in[0];
    const float* Wk = (const float*)d_in[1];
    // d_in[2] = bk: per-(b,h) additive constant on scores -> cancels in softmax, unused.
    const float* Wv = (const float*)d_in[3];
    const float* bv = (const float*)d_in[4];
    const float* q  = (const float*)d_in[5];
    float* out = (float*)d_out;

    cudaFuncSetAttribute(mha_main, cudaFuncAttributeMaxDynamicSharedMemorySize, SMEM_TOTAL);

    mha_prep<<<256, 256>>>(Wk, q);
    mha_main<<<NCTA, 256, SMEM_TOTAL>>>(kv, Wv, bv, out);
}

// round 13
// speedup vs baseline: 1.2405x; 1.0873x over previous
#include <cuda_runtime.h>
#include <cstdint>

typedef unsigned long long ull;

#define B_ 16
#define S_ 16384
#define C_ 256
#define NH_ 8
#define VD_ 64
#define CHB 18                            /* chunks per batch */
#define NCTA (B_ * CHB)                   /* 288 = 2 CTAs per SM, one wave */
#define PART_STRIDE 2080                  /* 2048 acc + 4 warps x 8 sums */
#define GROUPS_PER_B 512                  /* 32-row groups per batch */
#define NSTAGE 3
#define STAGE_ROWS 32
#define STAGE_BYTES (STAGE_ROWS * C_ * 4) /* 32768 */
#define LOG2E 1.4426950408889634f

/* dynamic smem layout */
#define SMW_OFF  (NSTAGE * STAGE_BYTES)               /* 98304: weights 3*4*4*8 ull = 3072B */
#define MBAR_OFF (SMW_OFF + 3072)                     /* 101376: 9 mbarriers */
#define SMEM_TOTAL (MBAR_OFF + 128)                   /* 101504 */

// Device-global scratch (no runtime allocation allowed).
__device__ __align__(16) float g_wqT[NH_ * C_];                  // (Wk @ q) * log2e, [h][c]
__device__ __align__(16) float g_part[(size_t)NCTA * PART_STRIDE];

// ---------------- packed f32x2 helpers ----------------
__device__ __forceinline__ ull f2fma(ull a, ull b, ull c) {
    ull d; asm("fma.rn.f32x2 %0,%1,%2,%3;" : "=l"(d) : "l"(a), "l"(b), "l"(c)); return d;
}
__device__ __forceinline__ ull f2mul(ull a, ull b) {
    ull d; asm("mul.rn.f32x2 %0,%1,%2;" : "=l"(d) : "l"(a), "l"(b)); return d;
}
__device__ __forceinline__ ull f2add(ull a, ull b) {
    ull d; asm("add.rn.f32x2 %0,%1,%2;" : "=l"(d) : "l"(a), "l"(b)); return d;
}
__device__ __forceinline__ ull pk(float x, float y) {
    ull r; asm("mov.b64 %0,{%1,%2};" : "=l"(r) : "f"(x), "f"(y)); return r;
}
__device__ __forceinline__ float2 upk(ull v) {
    float2 r; asm("mov.b64 {%0,%1},%2;" : "=f"(r.x), "=f"(r.y) : "l"(v)); return r;
}
__device__ __forceinline__ ull shx64(ull v, int m) {
    unsigned lo, hi;
    asm("mov.b64 {%0,%1},%2;" : "=r"(lo), "=r"(hi) : "l"(v));
    lo = __shfl_xor_sync(0xffffffffu, lo, m);
    hi = __shfl_xor_sync(0xffffffffu, hi, m);
    ull r; asm("mov.b64 %0,{%1,%2};" : "=l"(r) : "r"(lo), "r"(hi)); return r;
}

__device__ __forceinline__ uint32_t smem_u32(const void* p) {
    uint32_t a;
    asm("{ .reg .u64 t; cvta.to.shared.u64 t, %1; cvt.u32.u64 %0, t; }" : "=r"(a) : "l"(p));
    return a;
}

// ---------------- mbarrier / bulk-copy primitives ----------------
#define MBARRIER_INIT(mbar, cnt) \
    asm volatile("mbarrier.init.shared.b64 [%0], %1;" :: "r"(mbar), "r"((uint32_t)(cnt)) : "memory")
#define MBARRIER_ARRIVE(mbar) \
    asm volatile("mbarrier.arrive.shared.b64 _, [%0];" :: "r"(mbar) : "memory")
#define MBARRIER_EXPECT_TX(mbar, bytes) \
    asm volatile("mbarrier.arrive.expect_tx.shared.b64 _, [%0], %1;" :: "r"(mbar), "r"((uint32_t)(bytes)) : "memory")

#define MBARRIER_WAIT_PARITY(mbar, par) do {                                            \
    uint32_t _m = (mbar), _p = (uint32_t)(par), _done;                                  \
    asm volatile("{\n\t.reg .pred p;\n\t"                                               \
        "mbarrier.try_wait.parity.acquire.cta.shared::cta.b64 p, [%1], %2;\n\t"         \
        "selp.b32 %0, 1, 0, p;\n\t}"                                                    \
        : "=r"(_done) : "r"(_m), "r"(_p) : "memory");                                   \
    if (!_done) {                                                                       \
        asm volatile("{\n\t.reg .pred P1;\n\t"                                          \
            "WL_%=:\n\t"                                                                \
            "mbarrier.try_wait.parity.acquire.cta.shared::cta.b64 P1, [%0], %1, 0x989680;\n\t" \
            "@P1 bra.uni WD_%=;\n\t"                                                    \
            "bra.uni WL_%=;\n\t"                                                        \
            "WD_%=:\n\t}"                                                               \
            :: "r"(_m), "r"(_p) : "memory");                                            \
    }                                                                                   \
} while (0)

#define MBARRIER_WAIT_PARITY_RELAXED(mbar, par) do {                                    \
    uint32_t _m = (mbar), _p = (uint32_t)(par), _done;                                  \
    asm volatile("{\n\t.reg .pred p;\n\t"                                               \
        "mbarrier.try_wait.parity.relaxed.cta.shared::cta.b64 p, [%1], %2, 0x989680;\n\t" \
        "selp.b32 %0, 1, 0, p;\n\t}"                                                    \
        : "=r"(_done) : "r"(_m), "r"(_p) : "memory");                                   \
    if (!_done) {                                                                       \
        asm volatile("{\n\t.reg .pred P1;\n\t"                                          \
            "WL_%=:\n\t"                                                                \
            "mbarrier.try_wait.parity.relaxed.cta.shared::cta.b64 P1, [%0], %1, 0x989680;\n\t" \
            "@P1 bra.uni WD_%=;\n\t"                                                    \
            "bra.uni WL_%=;\n\t"                                                        \
            "WD_%=:\n\t}"                                                               \
            :: "r"(_m), "r"(_p) : "memory");                                            \
    }                                                                                   \
} while (0)

#define BULK_G2S(dst_u32, src_ptr, bytes, mbar) \
    asm volatile("cp.async.bulk.shared::cluster.global.mbarrier::complete_tx::bytes [%0], [%1], %2, [%3];" \
        :: "r"(dst_u32), "l"(src_ptr), "r"((uint32_t)(bytes)), "r"(mbar) : "memory")

// Value-halving warp reduction: 8 packed f32x2 values summed over 32 lanes.
// Afterwards, lane l holds the full-warp sum of value index (l>>2)&7.
__device__ __forceinline__ ull reduce8(ull v[8], int lane) {
    {
        bool hi = (lane & 16) != 0;
#pragma unroll
        for (int j = 0; j < 4; j++) {
            ull snd = hi ? v[j] : v[j + 4];
            ull kp  = hi ? v[j + 4] : v[j];
            v[j] = f2add(kp, shx64(snd, 16));
        }
    }
    {
        bool hi = (lane & 8) != 0;
#pragma unroll
        for (int j = 0; j < 2; j++) {
            ull snd = hi ? v[j] : v[j + 2];
            ull kp  = hi ? v[j + 2] : v[j];
            v[j] = f2add(kp, shx64(snd, 8));
        }
    }
    {
        bool hi = (lane & 4) != 0;
        ull snd = hi ? v[0] : v[1];
        ull kp  = hi ? v[1] : v[0];
        v[0] = f2add(kp, shx64(snd, 4));
    }
    v[0] = f2add(v[0], shx64(v[0], 2));
    v[0] = f2add(v[0], shx64(v[0], 1));
    return v[0];
}

// Conflict-free 2-row load: lane owns c in {4l..4l+3} and {128+4l..128+4l+3}.
__device__ __forceinline__ void load_row(ull out[4], const char* rowp, int lane) {
    ulonglong2 a0 = *reinterpret_cast<const ulonglong2*>(rowp + lane * 16);
    ulonglong2 a1 = *reinterpret_cast<const ulonglong2*>(rowp + 512 + lane * 16);
    out[0] = a0.x; out[1] = a0.y; out[2] = a1.x; out[3] = a1.y;
}

// Score FMA for a 2-row pair -> packed v[8] (per-head, rows in f32x2 lanes).
__device__ __forceinline__ void score_pair(const char* rbase, int r0, int lane,
                                           const ull wq2[4][NH_], ull v[8]) {
    ull kv0[4], kv1[4];
    load_row(kv0, rbase + r0 * 1024, lane);
    load_row(kv1, rbase + (r0 + 1) * 1024, lane);
    float s0[NH_];
    ull p[NH_];
#pragma unroll
    for (int h = 0; h < NH_; h++) p[h] = f2mul(kv0[0], wq2[0][h]);
#pragma unroll
    for (int j2 = 1; j2 < 4; j2++)
#pragma unroll
        for (int h = 0; h < NH_; h++) p[h] = f2fma(kv0[j2], wq2[j2][h], p[h]);
#pragma unroll
    for (int h = 0; h < NH_; h++) { float2 u2 = upk(p[h]); s0[h] = u2.x + u2.y; }
#pragma unroll
    for (int h = 0; h < NH_; h++) p[h] = f2mul(kv1[0], wq2[0][h]);
#pragma unroll
    for (int j2 = 1; j2 < 4; j2++)
#pragma unroll
        for (int h = 0; h < NH_; h++) p[h] = f2fma(kv1[j2], wq2[j2][h], p[h]);
#pragma unroll
    for (int h = 0; h < NH_; h++) { float2 u2 = upk(p[h]); v[h] = pk(s0[h], u2.x + u2.y); }
}

// ---------------- Kernel A: fold Wk @ q -> wq[h][c], scaled by log2e ----------------
__global__ void mha_prep(const float* __restrict__ Wk, const float* __restrict__ q) {
    int w = threadIdx.x >> 5, lane = threadIdx.x & 31;
    int idx = blockIdx.x * 8 + w;    // 0..2047 = h*256 + c
    int h = idx >> 8, c = idx & 255;
    float a = Wk[c * 512 + h * 64 + lane]      * q[h * 64 + lane]
            + Wk[c * 512 + h * 64 + lane + 32] * q[h * 64 + lane + 32];
#pragma unroll
    for (int m = 16; m; m >>= 1) a += __shfl_xor_sync(0xffffffffu, a, m);
    if (lane == 0) g_wqT[h * C_ + c] = a * LOG2E;
}

// ---------------- Kernel B: warp-specialized fused softmax-pool ----------------
// 4 score warps (w0-3) + 4 acc warps (w4-7); 3 x 32-row bulk-copy ring (96KB),
// all 3 slots prefetched. Producer = acc-warp-0 lane 0, issuing AFTER the
// empty-arrive of the slot it refills (near-zero empty-wait). Warp-elect
// mbarrier arrives (count 4) cut MIO arrive traffic 8x vs per-thread arrives.
__global__ void __launch_bounds__(256, 2) mha_main(const float* __restrict__ kv) {
    extern __shared__ __align__(128) char dsm[];
    char* sm_rows = dsm;
    ull*  sm_w    = reinterpret_cast<ull*>(dsm + SMW_OFF);    // [slot][warp][pair][h]

    const int tid  = threadIdx.x;
    const int w    = tid >> 5;
    const int lane = tid & 31;
    const int b  = blockIdx.x / CHB;
    const int ch = blockIdx.x % CHB;
    const int gstart = (ch * GROUPS_PER_B) / CHB;
    const int gend   = ((ch + 1) * GROUPS_PER_B) / CHB;
    const int ntiles = gend - gstart;

    const uint32_t mb_full = smem_u32(dsm + MBAR_OFF);
    const uint32_t mb_ws   = mb_full + NSTAGE * 8u;
    const uint32_t mb_emp  = mb_full + 2u * NSTAGE * 8u;
    const uint32_t rows_u32 = smem_u32(sm_rows);

    if (tid == 0) {
#pragma unroll
        for (int s = 0; s < NSTAGE; s++) {
            MBARRIER_INIT(mb_full + 8u * s, 1);
            MBARRIER_INIT(mb_ws   + 8u * s, 4);   // one elected arrive per score warp
            MBARRIER_INIT(mb_emp  + 8u * s, 4);   // one elected arrive per acc warp
        }
    }
    __syncthreads();

    const float* src = kv + ((size_t)b * S_ + (size_t)gstart * STAGE_ROWS) * C_;
    float* dst = g_part + (size_t)blockIdx.x * PART_STRIDE;

    // prologue: fill ALL 3 slots (ntiles >= 28 always)
    if (tid == 128) {
#pragma unroll
        for (int u = 0; u < NSTAGE; u++) {
            MBARRIER_EXPECT_TX(mb_full + 8u * u, STAGE_BYTES);
            BULK_G2S(rows_u32 + u * STAGE_BYTES, src + (size_t)u * STAGE_ROWS * C_,
                     STAGE_BYTES, mb_full + 8u * u);
        }
    }

    if (w < 4) {
        // ================= score warps =================
        ull wq2[4][NH_];
#pragma unroll
        for (int j2 = 0; j2 < 4; j2++) {
            const int cbase = (j2 < 2) ? (4 * lane + 2 * j2) : (128 + 4 * lane + 2 * (j2 - 2));
#pragma unroll
            for (int h = 0; h < NH_; h++)
                wq2[j2][h] = *reinterpret_cast<const ull*>(g_wqT + h * C_ + cbase);
        }

        ull sum2 = 0ull;
        int slot = 0, par = 0;
        for (int t = 0; t < ntiles; t++) {
            MBARRIER_WAIT_PARITY(mb_full + 8u * slot, par);
            const char* rbase = sm_rows + slot * STAGE_BYTES;

#pragma unroll
            for (int pair = 0; pair < 4; pair++) {
                ull v[8];
                score_pair(rbase, 8 * w + 2 * pair, lane, wq2, v);
                reduce8(v, lane);
                float2 e = upk(v[0]);
                asm("ex2.approx.f32 %0, %0;" : "+f"(e.x));
                asm("ex2.approx.f32 %0, %0;" : "+f"(e.y));
                ull wgt = pk(e.x, e.y);
                sum2 = f2add(sum2, wgt);
                if ((lane & 3) == 0)
                    sm_w[((slot * 4 + w) * 4 + pair) * NH_ + (lane >> 2)] = wgt;
            }
            __syncwarp();
            if (lane == 0) MBARRIER_ARRIVE(mb_ws + 8u * slot);
            if (++slot == NSTAGE) { slot = 0; par ^= 1; }
        }
        // per-warp head sums straight to gmem (combine sums the 4 warps)
        if ((lane & 3) == 0) {
            float2 sv = upk(sum2);
            dst[2048 + w * NH_ + (lane >> 2)] = sv.x + sv.y;
        }
    } else {
        // ============ acc warps (warp 4 lane 0 doubles as producer) ============
        const int wa = w - 4;
        ull acc2[NH_][4];
#pragma unroll
        for (int h = 0; h < NH_; h++)
#pragma unroll
            for (int j2 = 0; j2 < 4; j2++) acc2[h][j2] = 0ull;

        int slot = 0, par = 0;
        for (int t = 0; t < ntiles; t++) {
            MBARRIER_WAIT_PARITY(mb_ws + 8u * slot, par);
            const char* rbase = sm_rows + slot * STAGE_BYTES;

#pragma unroll
            for (int pair = 0; pair < 4; pair++) {
                const int r0 = 8 * wa + 2 * pair;
                ull kv0[4], kv1[4];
                load_row(kv0, rbase + r0 * 1024, lane);
                load_row(kv1, rbase + (r0 + 1) * 1024, lane);
#pragma unroll
                for (int h = 0; h < NH_; h++) {
                    ull wll = sm_w[((slot * 4 + wa) * 4 + pair) * NH_ + h];
                    float2 e = upk(wll);
                    ull a0 = pk(e.x, e.x), a1 = pk(e.y, e.y);
#pragma unroll
                    for (int j2 = 0; j2 < 4; j2++)
                        acc2[h][j2] = f2fma(a0, kv0[j2], f2fma(a1, kv1[j2], acc2[h][j2]));
                }
            }
            __syncwarp();
            if (lane == 0) MBARRIER_ARRIVE(mb_emp + 8u * slot);

            // refill the slot just freed with tile t+NSTAGE (producer thread)
            if (tid == 128) {
                const int u = t + NSTAGE;
                if (u < ntiles) {
                    MBARRIER_WAIT_PARITY_RELAXED(mb_emp + 8u * slot, par);
                    MBARRIER_EXPECT_TX(mb_full + 8u * slot, STAGE_BYTES);
                    BULK_G2S(rows_u32 + slot * STAGE_BYTES, src + (size_t)u * STAGE_ROWS * C_,
                             STAGE_BYTES, mb_full + 8u * slot);
                }
            }
            if (++slot == NSTAGE) { slot = 0; par ^= 1; }
        }

        // ---- acc-warps-only merge (score warps finished all slot reads earlier) ----
        asm volatile("bar.sync 1, 128;" ::: "memory");
        float* red = reinterpret_cast<float*>(sm_rows);   // [4][2048], absolute-c layout
#pragma unroll
        for (int h = 0; h < NH_; h++) {
            *reinterpret_cast<ull*>(&red[wa * 2048 + h * C_ + 4 * lane])           = acc2[h][0];
            *reinterpret_cast<ull*>(&red[wa * 2048 + h * C_ + 4 * lane + 2])       = acc2[h][1];
            *reinterpret_cast<ull*>(&red[wa * 2048 + h * C_ + 128 + 4 * lane])     = acc2[h][2];
            *reinterpret_cast<ull*>(&red[wa * 2048 + h * C_ + 128 + 4 * lane + 2]) = acc2[h][3];
        }
        asm volatile("bar.sync 1, 128;" ::: "memory");

        const int at = wa * 32 + lane;   // 0..127, each merges 16 floats
#pragma unroll
        for (int j = 0; j < 8; j++) {
            ull a = *reinterpret_cast<ull*>(&red[at * 16 + 2 * j]);
            a = f2add(a, *reinterpret_cast<ull*>(&red[2048 + at * 16 + 2 * j]));
            a = f2add(a, *reinterpret_cast<ull*>(&red[4096 + at * 16 + 2 * j]));
            a = f2add(a, *reinterpret_cast<ull*>(&red[6144 + at * 16 + 2 * j]));
            *reinterpret_cast<ull*>(dst + at * 16 + 2 * j) = a;
        }
    }
}

// ---------------- Kernel C: merge partials, normalize, project with Wv ----------------
__global__ void mha_combine(const float* __restrict__ Wv, const float* __restrict__ bv,
                            float* __restrict__ out) {
    const int b = blockIdx.x >> 3;
    const int h = blockIdx.x & 7;
    const int t = threadIdx.x;   // 256 threads

    __shared__ float m_s[C_];
    __shared__ float s_s[CHB * 4];
    __shared__ float gacc[4][VD_];

    const size_t base = (size_t)b * CHB * PART_STRIDE;
    float M = 0.f;
#pragma unroll
    for (int k = 0; k < CHB; k++)
        M += g_part[base + (size_t)k * PART_STRIDE + h * C_ + t];

    if (t < CHB * 4)
        s_s[t] = g_part[base + (size_t)(t >> 2) * PART_STRIDE + 2048 + (t & 3) * NH_ + h];
    __syncthreads();

    float S = 0.f;
#pragma unroll
    for (int k = 0; k < CHB * 4; k++) S += s_s[k];

    m_s[t] = M;   // unnormalized; divide once at the end
    __syncthreads();

    const int q  = t >> 6;    // c-quarter 0..3
    const int vd = t & 63;    // output dim
    float acc = 0.f;
#pragma unroll 8
    for (int i = 0; i < 64; i++) {
        int c = q * 64 + i;
        acc += m_s[c] * Wv[c * (NH_ * VD_) + h * VD_ + vd];   // coalesced across vd
    }
    gacc[q][vd] = acc;
    __syncthreads();

    if (t < VD_) {
        float r = (gacc[0][t] + gacc[1][t] + gacc[2][t] + gacc[3][t]) / S + bv[h * VD_ + t];
        out[(b * NH_ + h) * VD_ + t] = r;
    }
}

extern "C" void kernel_launch(void* const* d_in, const int* in_sizes, int n_in,
                              void* d_out, int out_size) {
    const float* kv = (const float*)d_in[0];
    const float* Wk = (const float*)d_in[1];
    // d_in[2] = bk: per-(b,h) additive constant on scores -> cancels in softmax, unused.
    const float* Wv = (const float*)d_in[3];
    const float* bv = (const float*)d_in[4];
    const float* q  = (const float*)d_in[5];
    float* out = (float*)d_out;

    cudaFuncSetAttribute(mha_main, cudaFuncAttributeMaxDynamicSharedMemorySize, SMEM_TOTAL);

    mha_prep<<<256, 256>>>(Wk, q);
    mha_main<<<NCTA, 256, SMEM_TOTAL>>>(kv);
    mha_combine<<<B_ * NH_, 256>>>(Wv, bv, out);
}

// round 15
// speedup vs baseline: 1.2606x; 1.0162x over previous
#include <cuda_runtime.h>
#include <cstdint>

typedef unsigned long long ull;

#define B_ 16
#define S_ 16384
#define C_ 256
#define NH_ 8
#define VD_ 64
#define CHB 18                            /* chunks per batch */
#define NCTA (B_ * CHB)                   /* 288 = 2 CTAs per SM, one wave */
#define PART_STRIDE 2080                  /* 2048 acc + 4 warps x 8 sums */
#define GROUPS_PER_B 512                  /* 32-row groups per batch */
#define NSTAGE 3
#define STAGE_ROWS 32
#define ROW_PITCH 1040                    /* 1024 + 16: 4-bank shift per row */
#define SLOT_STRIDE (STAGE_ROWS * ROW_PITCH)   /* 33280 */
#define STAGE_DATA (STAGE_ROWS * C_ * 4)       /* 32768 actual bytes per tile */
#define LOG2E 1.4426950408889634f

/* dynamic smem layout */
#define WSM_OFF  (NSTAGE * SLOT_STRIDE)               /* 99840: weights [slot][h][32] = 3KB */
#define MBAR_OFF (WSM_OFF + 3072)                     /* 102912: 9 mbarriers */
#define SMEM_TOTAL (MBAR_OFF + 128)                   /* 103040 */

// Device-global scratch (no runtime allocation allowed).
__device__ __align__(16) float g_wqT[NH_ * C_];   // tf32-rounded (Wk@q)*log2e, [h][c]
__device__ __align__(16) float g_part[(size_t)NCTA * PART_STRIDE];

// ---------------- packed f32x2 helpers ----------------
__device__ __forceinline__ ull f2fma(ull a, ull b, ull c) {
    ull d; asm("fma.rn.f32x2 %0,%1,%2,%3;" : "=l"(d) : "l"(a), "l"(b), "l"(c)); return d;
}
__device__ __forceinline__ ull f2add(ull a, ull b) {
    ull d; asm("add.rn.f32x2 %0,%1,%2;" : "=l"(d) : "l"(a), "l"(b)); return d;
}
__device__ __forceinline__ ull pk(float x, float y) {
    ull r; asm("mov.b64 %0,{%1,%2};" : "=l"(r) : "f"(x), "f"(y)); return r;
}
__device__ __forceinline__ float2 upk(ull v) {
    float2 r; asm("mov.b64 {%0,%1},%2;" : "=f"(r.x), "=f"(r.y) : "l"(v)); return r;
}

__device__ __forceinline__ uint32_t smem_u32(const void* p) {
    uint32_t a;
    asm("{ .reg .u64 t; cvta.to.shared.u64 t, %1; cvt.u32.u64 %0, t; }" : "=r"(a) : "l"(p));
    return a;
}

// ---------------- mbarrier / bulk-copy primitives ----------------
#define MBARRIER_INIT(mbar, cnt) \
    asm volatile("mbarrier.init.shared.b64 [%0], %1;" :: "r"(mbar), "r"((uint32_t)(cnt)) : "memory")
#define MBARRIER_ARRIVE(mbar) \
    asm volatile("mbarrier.arrive.shared.b64 _, [%0];" :: "r"(mbar) : "memory")
#define MBARRIER_EXPECT_TX(mbar, bytes) \
    asm volatile("mbarrier.arrive.expect_tx.shared.b64 _, [%0], %1;" :: "r"(mbar), "r"((uint32_t)(bytes)) : "memory")

#define MBARRIER_WAIT_PARITY(mbar, par) do {                                            \
    uint32_t _m = (mbar), _p = (uint32_t)(par), _done;                                  \
    asm volatile("{\n\t.reg .pred p;\n\t"                                               \
        "mbarrier.try_wait.parity.acquire.cta.shared::cta.b64 p, [%1], %2;\n\t"         \
        "selp.b32 %0, 1, 0, p;\n\t}"                                                    \
        : "=r"(_done) : "r"(_m), "r"(_p) : "memory");                                   \
    if (!_done) {                                                                       \
        asm volatile("{\n\t.reg .pred P1;\n\t"                                          \
            "WL_%=:\n\t"                                                                \
            "mbarrier.try_wait.parity.acquire.cta.shared::cta.b64 P1, [%0], %1, 0x989680;\n\t" \
            "@P1 bra.uni WD_%=;\n\t"                                                    \
            "bra.uni WL_%=;\n\t"                                                        \
            "WD_%=:\n\t}"                                                               \
            :: "r"(_m), "r"(_p) : "memory");                                            \
    }                                                                                   \
} while (0)

#define MBARRIER_WAIT_PARITY_RELAXED(mbar, par) do {                                    \
    uint32_t _m = (mbar), _p = (uint32_t)(par), _done;                                  \
    asm volatile("{\n\t.reg .pred p;\n\t"                                               \
        "mbarrier.try_wait.parity.relaxed.cta.shared::cta.b64 p, [%1], %2, 0x989680;\n\t" \
        "selp.b32 %0, 1, 0, p;\n\t}"                                                    \
        : "=r"(_done) : "r"(_m), "r"(_p) : "memory");                                   \
    if (!_done) {                                                                       \
        asm volatile("{\n\t.reg .pred P1;\n\t"                                          \
            "WL_%=:\n\t"                                                                \
            "mbarrier.try_wait.parity.relaxed.cta.shared::cta.b64 P1, [%0], %1, 0x989680;\n\t" \
            "@P1 bra.uni WD_%=;\n\t"                                                    \
            "bra.uni WL_%=;\n\t"                                                        \
            "WD_%=:\n\t}"                                                               \
            :: "r"(_m), "r"(_p) : "memory");                                            \
    }                                                                                   \
} while (0)

#define BULK_G2S(dst_u32, src_ptr, bytes, mbar) \
    asm volatile("cp.async.bulk.shared::cluster.global.mbarrier::complete_tx::bytes [%0], [%1], %2, [%3];" \
        :: "r"(dst_u32), "l"(src_ptr), "r"((uint32_t)(bytes)), "r"(mbar) : "memory")

// Conflict-free 2-row load: lane owns c in {4l..4l+3} and {128+4l..128+4l+3}.
__device__ __forceinline__ void load_row(ull out[4], const char* rowp, int lane) {
    ulonglong2 a0 = *reinterpret_cast<const ulonglong2*>(rowp + lane * 16);
    ulonglong2 a1 = *reinterpret_cast<const ulonglong2*>(rowp + 512 + lane * 16);
    out[0] = a0.x; out[1] = a0.y; out[2] = a1.x; out[3] = a1.y;
}

// ---------------- Kernel A: fold Wk @ q -> wq[h][c] * log2e, tf32-rounded ----------------
__global__ void mha_prep(const float* __restrict__ Wk, const float* __restrict__ q) {
    int w = threadIdx.x >> 5, lane = threadIdx.x & 31;
    int idx = blockIdx.x * 8 + w;    // 0..2047 = h*256 + c
    int h = idx >> 8, c = idx & 255;
    float a = Wk[c * 512 + h * 64 + lane]      * q[h * 64 + lane]
            + Wk[c * 512 + h * 64 + lane + 32] * q[h * 64 + lane + 32];
#pragma unroll
    for (int m = 16; m; m >>= 1) a += __shfl_xor_sync(0xffffffffu, a, m);
    if (lane == 0) {
        float s = a * LOG2E;
        uint32_t t;
        asm("cvt.rna.tf32.f32 %0, %1;" : "=r"(t) : "f"(s));   // round wq to tf32 once
        g_wqT[h * C_ + c] = __uint_as_float(t);
    }
}

// ---------------- Kernel B: tensor-core (mma.sync tf32) scores + scalar accumulation ----
// 4 score warps (w0-3): one m16n8k8 per 8 rows x 8 heads, A=wq frags in registers.
// 4 acc warps (w4-7): pure f32x2 FMA. 3 x 32-row ring, ROW_PITCH=1040 for
// conflict-free B-fragment LDS (bank = 4g + tig + 8k, all 32 distinct).
__global__ void __launch_bounds__(256, 2) mha_main(const float* __restrict__ kv) {
    extern __shared__ __align__(128) char dsm[];
    float* wsm = reinterpret_cast<float*>(dsm + WSM_OFF);   // [slot][h][32]

    const int tid  = threadIdx.x;
    const int w    = tid >> 5;
    const int lane = tid & 31;
    const int b  = blockIdx.x / CHB;
    const int ch = blockIdx.x % CHB;
    const int gstart = (ch * GROUPS_PER_B) / CHB;
    const int gend   = ((ch + 1) * GROUPS_PER_B) / CHB;
    const int ntiles = gend - gstart;

    const uint32_t mb_full = smem_u32(dsm + MBAR_OFF);
    const uint32_t mb_ws   = mb_full + NSTAGE * 8u;
    const uint32_t mb_emp  = mb_full + 2u * NSTAGE * 8u;
    const uint32_t rows_u32 = smem_u32(dsm);

    if (tid == 0) {
#pragma unroll
        for (int s = 0; s < NSTAGE; s++) {
            MBARRIER_INIT(mb_full + 8u * s, 1);
            MBARRIER_INIT(mb_ws   + 8u * s, 4);   // one elected arrive per score warp
            MBARRIER_INIT(mb_emp  + 8u * s, 4);   // one elected arrive per acc warp
        }
    }
    __syncthreads();

    const float* src = kv + ((size_t)b * S_ + (size_t)gstart * STAGE_ROWS) * C_;
    float* dst = g_part + (size_t)blockIdx.x * PART_STRIDE;

    // prologue: fill ALL 3 slots (row-by-row copies for the padded pitch)
    if (tid == 128) {
#pragma unroll
        for (int u = 0; u < NSTAGE; u++) {
            MBARRIER_EXPECT_TX(mb_full + 8u * u, STAGE_DATA);
            const float* ts = src + (size_t)u * STAGE_ROWS * C_;
            const uint32_t db = rows_u32 + u * SLOT_STRIDE;
            for (int r = 0; r < STAGE_ROWS; r++)
                BULK_G2S(db + r * ROW_PITCH, ts + r * C_, 1024, mb_full + 8u * u);
        }
    }

    if (w < 4) {
        // ================= score warps (mma.sync tf32) =================
        const int g   = lane >> 2;   // head 0..7 (A rows), also B col for loads
        const int tig = lane & 3;

        // A fragments: a0[k] = wq[g][8k+tig], a2[k] = wq[g][8k+tig+4]; rows 8-15 zero.
        uint32_t a0f[32], a2f[32];
        {
            const uint32_t* wqu = reinterpret_cast<const uint32_t*>(g_wqT) + g * C_ + tig;
#pragma unroll
            for (int k = 0; k < 32; k++) { a0f[k] = wqu[8 * k]; a2f[k] = wqu[8 * k + 4]; }
        }

        float sacc = 0.f;
        int slot = 0, par = 0;
        for (int t = 0; t < ntiles; t++) {
            MBARRIER_WAIT_PARITY(mb_full + 8u * slot, par);
            // this lane's B base: kv row (8w+g), channel tig
            const char* lanep = dsm + slot * SLOT_STRIDE + (8 * w + g) * ROW_PITCH + tig * 4;

            float cc[4][4];
#pragma unroll
            for (int q = 0; q < 4; q++)
#pragma unroll
                for (int j = 0; j < 4; j++) cc[q][j] = 0.f;

#pragma unroll
            for (int i = 0; i < 8; i++) {
#pragma unroll
                for (int q = 0; q < 4; q++) {
                    const int k = 4 * i + q;
                    uint32_t b0 = *reinterpret_cast<const uint32_t*>(lanep + 32 * k);
                    uint32_t b1 = *reinterpret_cast<const uint32_t*>(lanep + 32 * k + 16);
                    asm volatile(
                        "mma.sync.aligned.m16n8k8.row.col.f32.tf32.tf32.f32 "
                        "{%0,%1,%2,%3}, {%4,%5,%6,%7}, {%8,%9}, {%0,%1,%2,%3};"
                        : "+f"(cc[q][0]), "+f"(cc[q][1]), "+f"(cc[q][2]), "+f"(cc[q][3])
                        : "r"(a0f[k]), "r"(0u), "r"(a2f[k]), "r"(0u), "r"(b0), "r"(b1));
                }
            }
            // scores: head g, rows (8w+2tig, 8w+2tig+1)
            float s0 = (cc[0][0] + cc[1][0]) + (cc[2][0] + cc[3][0]);
            float s1 = (cc[0][1] + cc[1][1]) + (cc[2][1] + cc[3][1]);
            asm("ex2.approx.f32 %0, %0;" : "+f"(s0));
            asm("ex2.approx.f32 %0, %0;" : "+f"(s1));
            sacc += s0 + s1;

            {
                uint32_t wa = smem_u32(wsm + slot * 256 + g * 32 + 8 * w + 2 * tig);
                asm volatile("st.shared.v2.f32 [%0], {%1,%2};" :: "r"(wa), "f"(s0), "f"(s1) : "memory");
            }
            __syncwarp();
            if (lane == 0) MBARRIER_ARRIVE(mb_ws + 8u * slot);
            if (++slot == NSTAGE) { slot = 0; par ^= 1; }
        }
        // per-warp per-head weight sums -> gmem (sum over the 4 tig lanes of each head)
        float v = sacc;
        v += __shfl_xor_sync(0xffffffffu, v, 1);
        v += __shfl_xor_sync(0xffffffffu, v, 2);
        if ((lane & 3) == 0) dst[2048 + w * NH_ + g] = v;
    } else {
        // ============ acc warps (warp 4 lane 0 doubles as producer) ============
        const int wa = w - 4;
        ull acc2[NH_][4];
#pragma unroll
        for (int h = 0; h < NH_; h++)
#pragma unroll
            for (int j2 = 0; j2 < 4; j2++) acc2[h][j2] = 0ull;

        int slot = 0, par = 0;
        for (int t = 0; t < ntiles; t++) {
            MBARRIER_WAIT_PARITY(mb_ws + 8u * slot, par);
            const char* rbase = dsm + slot * SLOT_STRIDE;

#pragma unroll
            for (int pair = 0; pair < 4; pair++) {
                const int r0 = 8 * wa + 2 * pair;
                ull kv0[4], kv1[4];
                load_row(kv0, rbase + r0 * ROW_PITCH, lane);
                load_row(kv1, rbase + (r0 + 1) * ROW_PITCH, lane);
#pragma unroll
                for (int h = 0; h < NH_; h++) {
                    ull wll = *reinterpret_cast<const ull*>(&wsm[slot * 256 + h * 32 + r0]);
                    float2 e = upk(wll);
                    ull a0 = pk(e.x, e.x), a1 = pk(e.y, e.y);
#pragma unroll
                    for (int j2 = 0; j2 < 4; j2++)
                        acc2[h][j2] = f2fma(a0, kv0[j2], f2fma(a1, kv1[j2], acc2[h][j2]));
                }
            }
            __syncwarp();
            if (lane == 0) MBARRIER_ARRIVE(mb_emp + 8u * slot);

            // refill the slot just freed with tile t+NSTAGE (producer thread)
            if (tid == 128) {
                const int u = t + NSTAGE;
                if (u < ntiles) {
                    MBARRIER_WAIT_PARITY_RELAXED(mb_emp + 8u * slot, par);
                    MBARRIER_EXPECT_TX(mb_full + 8u * slot, STAGE_DATA);
                    const float* ts = src + (size_t)u * STAGE_ROWS * C_;
                    const uint32_t db = rows_u32 + slot * SLOT_STRIDE;
                    for (int r = 0; r < STAGE_ROWS; r++)
                        BULK_G2S(db + r * ROW_PITCH, ts + r * C_, 1024, mb_full + 8u * slot);
                }
            }
            if (++slot == NSTAGE) { slot = 0; par ^= 1; }
        }

        // ---- acc-warps-only merge (score warps finished all slot reads earlier) ----
        asm volatile("bar.sync 1, 128;" ::: "memory");
        float* red = reinterpret_cast<float*>(dsm);   // [4][2048], absolute-c layout
#pragma unroll
        for (int h = 0; h < NH_; h++) {
            *reinterpret_cast<ull*>(&red[wa * 2048 + h * C_ + 4 * lane])           = acc2[h][0];
            *reinterpret_cast<ull*>(&red[wa * 2048 + h * C_ + 4 * lane + 2])       = acc2[h][1];
            *reinterpret_cast<ull*>(&red[wa * 2048 + h * C_ + 128 + 4 * lane])     = acc2[h][2];
            *reinterpret_cast<ull*>(&red[wa * 2048 + h * C_ + 128 + 4 * lane + 2]) = acc2[h][3];
        }
        asm volatile("bar.sync 1, 128;" ::: "memory");

        const int at = wa * 32 + lane;   // 0..127, each merges 16 floats
#pragma unroll
        for (int j = 0; j < 8; j++) {
            ull a = *reinterpret_cast<ull*>(&red[at * 16 + 2 * j]);
            a = f2add(a, *reinterpret_cast<ull*>(&red[2048 + at * 16 + 2 * j]));
            a = f2add(a, *reinterpret_cast<ull*>(&red[4096 + at * 16 + 2 * j]));
            a = f2add(a, *reinterpret_cast<ull*>(&red[6144 + at * 16 + 2 * j]));
            *reinterpret_cast<ull*>(dst + at * 16 + 2 * j) = a;
        }
    }
}

// ---------------- Kernel C: merge partials, normalize, project with Wv ----------------
__global__ void mha_combine(const float* __restrict__ Wv, const float* __restrict__ bv,
                            float* __restrict__ out) {
    const int b = blockIdx.x >> 3;
    const int h = blockIdx.x & 7;
    const int t = threadIdx.x;   // 256 threads

    __shared__ float m_s[C_];
    __shared__ float s_s[CHB * 4];
    __shared__ float gacc[4][VD_];

    const size_t base = (size_t)b * CHB * PART_STRIDE;
    float M = 0.f;
#pragma unroll
    for (int k = 0; k < CHB; k++)
        M += g_part[base + (size_t)k * PART_STRIDE + h * C_ + t];

    if (t < CHB * 4)
        s_s[t] = g_part[base + (size_t)(t >> 2) * PART_STRIDE + 2048 + (t & 3) * NH_ + h];
    __syncthreads();

    float S = 0.f;
#pragma unroll
    for (int k = 0; k < CHB * 4; k++) S += s_s[k];

    m_s[t] = M;   // unnormalized; divide once at the end
    __syncthreads();

    const int q  = t >> 6;    // c-quarter 0..3
    const int vd = t & 63;    // output dim
    float acc = 0.f;
#pragma unroll 8
    for (int i = 0; i < 64; i++) {
        int c = q * 64 + i;
        acc += m_s[c] * Wv[c * (NH_ * VD_) + h * VD_ + vd];   // coalesced across vd
    }
    gacc[q][vd] = acc;
    __syncthreads();

    if (t < VD_) {
        float r = (gacc[0][t] + gacc[1][t] + gacc[2][t] + gacc[3][t]) / S + bv[h * VD_ + t];
        out[(b * NH_ + h) * VD_ + t] = r;
    }
}

extern "C" void kernel_launch(void* const* d_in, const int* in_sizes, int n_in,
                              void* d_out, int out_size) {
    const float* kv = (const float*)d_in[0];
    const float* Wk = (const float*)d_in[1];
    // d_in[2] = bk: per-(b,h) additive constant on scores -> cancels in softmax, unused.
    const float* Wv = (const float*)d_in[3];
    const float* bv = (const float*)d_in[4];
    const float* q  = (const float*)d_in[5];
    float* out = (float*)d_out;

    cudaFuncSetAttribute(mha_main, cudaFuncAttributeMaxDynamicSharedMemorySize, SMEM_TOTAL);

    mha_prep<<<256, 256>>>(Wk, q);
    mha_main<<<NCTA, 256, SMEM_TOTAL>>>(kv);
    mha_combine<<<B_ * NH_, 256>>>(Wv, bv, out);
}

// round 16
// speedup vs baseline: 1.3109x; 1.0399x over previous
#include <cuda_runtime.h>
#include <cstdint>

typedef unsigned long long ull;

#define B_ 16
#define S_ 16384
#define C_ 256
#define NH_ 8
#define VD_ 64
#define CHB 18                            /* chunks per batch */
#define NCTA (B_ * CHB)                   /* 288 = 2 CTAs per SM, one wave */
#define PART_STRIDE 2080                  /* 2048 acc + 4 warps x 8 sums */
#define GROUPS_PER_B 512                  /* 32-row groups per batch */
#define NSTAGE 3
#define STAGE_ROWS 32
#define ROW_PITCH 1040                    /* 1024 + 16: 4-bank shift per row */
#define SLOT_STRIDE (STAGE_ROWS * ROW_PITCH)   /* 33280 */
#define WARP_BYTES (8 * C_ * 4)                /* 8192: one acc warp's 8 rows */
#define LOG2E 1.4426950408889634f

/* dynamic smem layout */
#define WSM_OFF  (NSTAGE * SLOT_STRIDE)               /* 99840: weights [slot][h][32] = 3KB */
#define MBAR_OFF (WSM_OFF + 3072)                     /* 102912: 9 mbarriers */
#define SMEM_TOTAL (MBAR_OFF + 128)                   /* 103040 */

// Device-global scratch (no runtime allocation allowed).
__device__ __align__(16) float g_wqT[NH_ * C_];   // tf32-rounded (Wk@q)*log2e, [h][c]
__device__ __align__(16) float g_part[(size_t)NCTA * PART_STRIDE];

// ---------------- packed f32x2 helpers ----------------
__device__ __forceinline__ ull f2fma(ull a, ull b, ull c) {
    ull d; asm("fma.rn.f32x2 %0,%1,%2,%3;" : "=l"(d) : "l"(a), "l"(b), "l"(c)); return d;
}
__device__ __forceinline__ ull f2add(ull a, ull b) {
    ull d; asm("add.rn.f32x2 %0,%1,%2;" : "=l"(d) : "l"(a), "l"(b)); return d;
}
__device__ __forceinline__ ull pk(float x, float y) {
    ull r; asm("mov.b64 %0,{%1,%2};" : "=l"(r) : "f"(x), "f"(y)); return r;
}
__device__ __forceinline__ float2 upk(ull v) {
    float2 r; asm("mov.b64 {%0,%1},%2;" : "=f"(r.x), "=f"(r.y) : "l"(v)); return r;
}

__device__ __forceinline__ uint32_t smem_u32(const void* p) {
    uint32_t a;
    asm("{ .reg .u64 t; cvta.to.shared.u64 t, %1; cvt.u32.u64 %0, t; }" : "=r"(a) : "l"(p));
    return a;
}

// ---------------- mbarrier / bulk-copy primitives ----------------
#define MBARRIER_INIT(mbar, cnt) \
    asm volatile("mbarrier.init.shared.b64 [%0], %1;" :: "r"(mbar), "r"((uint32_t)(cnt)) : "memory")
#define MBARRIER_ARRIVE(mbar) \
    asm volatile("mbarrier.arrive.shared.b64 _, [%0];" :: "r"(mbar) : "memory")
#define MBARRIER_EXPECT_TX(mbar, bytes) \
    asm volatile("mbarrier.arrive.expect_tx.shared.b64 _, [%0], %1;" :: "r"(mbar), "r"((uint32_t)(bytes)) : "memory")

#define MBARRIER_WAIT_PARITY(mbar, par) do {                                            \
    uint32_t _m = (mbar), _p = (uint32_t)(par), _done;                                  \
    asm volatile("{\n\t.reg .pred p;\n\t"                                               \
        "mbarrier.try_wait.parity.acquire.cta.shared::cta.b64 p, [%1], %2;\n\t"         \
        "selp.b32 %0, 1, 0, p;\n\t}"                                                    \
        : "=r"(_done) : "r"(_m), "r"(_p) : "memory");                                   \
    if (!_done) {                                                                       \
        asm volatile("{\n\t.reg .pred P1;\n\t"                                          \
            "WL_%=:\n\t"                                                                \
            "mbarrier.try_wait.parity.acquire.cta.shared::cta.b64 P1, [%0], %1, 0x989680;\n\t" \
            "@P1 bra.uni WD_%=;\n\t"                                                    \
            "bra.uni WL_%=;\n\t"                                                        \
            "WD_%=:\n\t}"                                                               \
            :: "r"(_m), "r"(_p) : "memory");                                            \
    }                                                                                   \
} while (0)

#define MBARRIER_WAIT_PARITY_RELAXED(mbar, par) do {                                    \
    uint32_t _m = (mbar), _p = (uint32_t)(par), _done;                                  \
    asm volatile("{\n\t.reg .pred p;\n\t"                                               \
        "mbarrier.try_wait.parity.relaxed.cta.shared::cta.b64 p, [%1], %2, 0x989680;\n\t" \
        "selp.b32 %0, 1, 0, p;\n\t}"                                                    \
        : "=r"(_done) : "r"(_m), "r"(_p) : "memory");                                   \
    if (!_done) {                                                                       \
        asm volatile("{\n\t.reg .pred P1;\n\t"                                          \
            "WL_%=:\n\t"                                                                \
            "mbarrier.try_wait.parity.relaxed.cta.shared::cta.b64 P1, [%0], %1, 0x989680;\n\t" \
            "@P1 bra.uni WD_%=;\n\t"                                                    \
            "bra.uni WL_%=;\n\t"                                                        \
            "WD_%=:\n\t}"                                                               \
            :: "r"(_m), "r"(_p) : "memory");                                            \
    }                                                                                   \
} while (0)

#define BULK_G2S(dst_u32, src_ptr, bytes, mbar) \
    asm volatile("cp.async.bulk.shared::cluster.global.mbarrier::complete_tx::bytes [%0], [%1], %2, [%3];" \
        :: "r"(dst_u32), "l"(src_ptr), "r"((uint32_t)(bytes)), "r"(mbar) : "memory")

// Conflict-free 2-row load: lane owns c in {4l..4l+3} and {128+4l..128+4l+3}.
__device__ __forceinline__ void load_row(ull out[4], const char* rowp, int lane) {
    ulonglong2 a0 = *reinterpret_cast<const ulonglong2*>(rowp + lane * 16);
    ulonglong2 a1 = *reinterpret_cast<const ulonglong2*>(rowp + 512 + lane * 16);
    out[0] = a0.x; out[1] = a0.y; out[2] = a1.x; out[3] = a1.y;
}

// ---------------- Kernel A: fold Wk @ q -> wq[h][c] * log2e, tf32-rounded ----------------
__global__ void mha_prep(const float* __restrict__ Wk, const float* __restrict__ q) {
    int w = threadIdx.x >> 5, lane = threadIdx.x & 31;
    int idx = blockIdx.x * 8 + w;    // 0..2047 = h*256 + c
    int h = idx >> 8, c = idx & 255;
    float a = Wk[c * 512 + h * 64 + lane]      * q[h * 64 + lane]
            + Wk[c * 512 + h * 64 + lane + 32] * q[h * 64 + lane + 32];
#pragma unroll
    for (int m = 16; m; m >>= 1) a += __shfl_xor_sync(0xffffffffu, a, m);
    if (lane == 0) {
        float s = a * LOG2E;
        uint32_t t;
        asm("cvt.rna.tf32.f32 %0, %1;" : "=r"(t) : "f"(s));   // round wq to tf32 once
        g_wqT[h * C_ + c] = __uint_as_float(t);
    }
}

// ---------------- Kernel B: tensor-core (mma.sync tf32) scores + scalar accumulation ----
// 4 score warps (w0-3): one m16n8k8 chain per 8 rows x 8 heads, A=wq frags in registers.
// 4 acc warps (w4-7): pure f32x2 FMA; EACH acc warp is also the TMA producer for its
// own 8 rows (distributed expect_tx, mb_full count=4). 3 x 32-row ring, ROW_PITCH=1040.
__global__ void __launch_bounds__(256, 2) mha_main(const float* __restrict__ kv) {
    extern __shared__ __align__(128) char dsm[];
    float* wsm = reinterpret_cast<float*>(dsm + WSM_OFF);   // [slot][h][32]

    const int tid  = threadIdx.x;
    const int w    = tid >> 5;
    const int lane = tid & 31;
    const int b  = blockIdx.x / CHB;
    const int ch = blockIdx.x % CHB;
    const int gstart = (ch * GROUPS_PER_B) / CHB;
    const int gend   = ((ch + 1) * GROUPS_PER_B) / CHB;
    const int ntiles = gend - gstart;

    const uint32_t mb_full = smem_u32(dsm + MBAR_OFF);
    const uint32_t mb_ws   = mb_full + NSTAGE * 8u;
    const uint32_t mb_emp  = mb_full + 2u * NSTAGE * 8u;
    const uint32_t rows_u32 = smem_u32(dsm);

    if (tid == 0) {
#pragma unroll
        for (int s = 0; s < NSTAGE; s++) {
            MBARRIER_INIT(mb_full + 8u * s, 4);   // 4 distributed expect_tx arrives
            MBARRIER_INIT(mb_ws   + 8u * s, 4);   // one elected arrive per score warp
            MBARRIER_INIT(mb_emp  + 8u * s, 4);   // one elected arrive per acc warp
        }
    }
    __syncthreads();

    const float* src = kv + ((size_t)b * S_ + (size_t)gstart * STAGE_ROWS) * C_;
    float* dst = g_part + (size_t)blockIdx.x * PART_STRIDE;

    if (w < 4) {
        // ================= score warps (mma.sync tf32) =================
        const int g   = lane >> 2;   // head 0..7 (A rows), also B row-group for loads
        const int tig = lane & 3;

        // A fragments: a0[k] = wq[g][8k+tig], a2[k] = wq[g][8k+tig+4]; rows 8-15 zero.
        uint32_t a0f[32], a2f[32];
        {
            const uint32_t* wqu = reinterpret_cast<const uint32_t*>(g_wqT) + g * C_ + tig;
#pragma unroll
            for (int k = 0; k < 32; k++) { a0f[k] = wqu[8 * k]; a2f[k] = wqu[8 * k + 4]; }
        }

        float sacc = 0.f;
        int slot = 0, par = 0;
        for (int t = 0; t < ntiles; t++) {
            MBARRIER_WAIT_PARITY(mb_full + 8u * slot, par);
            // this lane's B base: kv row (8w+g), channel tig
            const char* lanep = dsm + slot * SLOT_STRIDE + (8 * w + g) * ROW_PITCH + tig * 4;

            float cc[4][4];
#pragma unroll
            for (int q = 0; q < 4; q++)
#pragma unroll
                for (int j = 0; j < 4; j++) cc[q][j] = 0.f;

#pragma unroll
            for (int i = 0; i < 8; i++) {
#pragma unroll
                for (int q = 0; q < 4; q++) {
                    const int k = 4 * i + q;
                    uint32_t b0 = *reinterpret_cast<const uint32_t*>(lanep + 32 * k);
                    uint32_t b1 = *reinterpret_cast<const uint32_t*>(lanep + 32 * k + 16);
                    asm volatile(
                        "mma.sync.aligned.m16n8k8.row.col.f32.tf32.tf32.f32 "
                        "{%0,%1,%2,%3}, {%4,%5,%6,%7}, {%8,%9}, {%0,%1,%2,%3};"
                        : "+f"(cc[q][0]), "+f"(cc[q][1]), "+f"(cc[q][2]), "+f"(cc[q][3])
                        : "r"(a0f[k]), "r"(0u), "r"(a2f[k]), "r"(0u), "r"(b0), "r"(b1));
                }
            }
            // scores: head g, rows (8w+2tig, 8w+2tig+1)
            float s0 = (cc[0][0] + cc[1][0]) + (cc[2][0] + cc[3][0]);
            float s1 = (cc[0][1] + cc[1][1]) + (cc[2][1] + cc[3][1]);
            asm("ex2.approx.f32 %0, %0;" : "+f"(s0));
            asm("ex2.approx.f32 %0, %0;" : "+f"(s1));
            sacc += s0 + s1;

            {
                uint32_t wa = smem_u32(wsm + slot * 256 + g * 32 + 8 * w + 2 * tig);
                asm volatile("st.shared.v2.f32 [%0], {%1,%2};" :: "r"(wa), "f"(s0), "f"(s1) : "memory");
            }
            __syncwarp();
            if (lane == 0) MBARRIER_ARRIVE(mb_ws + 8u * slot);
            if (++slot == NSTAGE) { slot = 0; par ^= 1; }
        }
        // per-warp per-head weight sums -> gmem (sum over the 4 tig lanes of each head)
        float v = sacc;
        v += __shfl_xor_sync(0xffffffffu, v, 1);
        v += __shfl_xor_sync(0xffffffffu, v, 2);
        if ((lane & 3) == 0) dst[2048 + w * NH_ + g] = v;
    } else {
        // ============ acc warps: FMA + distributed TMA production ============
        const int wa = w - 4;                     // 0..7 -> rows 8wa..8wa+7
        const float*   my_src  = src + 8 * wa * C_;                 // this warp's rows
        const uint32_t my_dsm  = rows_u32 + 8 * wa * ROW_PITCH;

        // distributed prologue: each acc warp loads its 8 rows of all 3 slots
        if (lane == 0) {
#pragma unroll
            for (int u = 0; u < NSTAGE; u++) {
                MBARRIER_EXPECT_TX(mb_full + 8u * u, WARP_BYTES);
                const float* ts = my_src + (size_t)u * STAGE_ROWS * C_;
                const uint32_t db = my_dsm + u * SLOT_STRIDE;
#pragma unroll
                for (int r = 0; r < 8; r++)
                    BULK_G2S(db + r * ROW_PITCH, ts + r * C_, 1024, mb_full + 8u * u);
            }
        }

        ull acc2[NH_][4];
#pragma unroll
        for (int h = 0; h < NH_; h++)
#pragma unroll
            for (int j2 = 0; j2 < 4; j2++) acc2[h][j2] = 0ull;

        int slot = 0, par = 0;
        for (int t = 0; t < ntiles; t++) {
            MBARRIER_WAIT_PARITY(mb_ws + 8u * slot, par);
            const char* rbase = dsm + slot * SLOT_STRIDE;

#pragma unroll
            for (int pair = 0; pair < 4; pair++) {
                const int r0 = 8 * wa + 2 * pair;
                ull kv0[4], kv1[4];
                load_row(kv0, rbase + r0 * ROW_PITCH, lane);
                load_row(kv1, rbase + (r0 + 1) * ROW_PITCH, lane);
#pragma unroll
                for (int h = 0; h < NH_; h++) {
                    ull wll = *reinterpret_cast<const ull*>(&wsm[slot * 256 + h * 32 + r0]);
                    float2 e = upk(wll);
                    ull a0 = pk(e.x, e.x), a1 = pk(e.y, e.y);
#pragma unroll
                    for (int j2 = 0; j2 < 4; j2++)
                        acc2[h][j2] = f2fma(a0, kv0[j2], f2fma(a1, kv1[j2], acc2[h][j2]));
                }
            }
            __syncwarp();
            if (lane == 0) {
                MBARRIER_ARRIVE(mb_emp + 8u * slot);
                // refill own 8 rows of this slot with tile t+NSTAGE
                const int u = t + NSTAGE;
                if (u < ntiles) {
                    MBARRIER_WAIT_PARITY_RELAXED(mb_emp + 8u * slot, par);
                    MBARRIER_EXPECT_TX(mb_full + 8u * slot, WARP_BYTES);
                    const float* ts = my_src + (size_t)u * STAGE_ROWS * C_;
                    const uint32_t db = my_dsm + slot * SLOT_STRIDE;
#pragma unroll
                    for (int r = 0; r < 8; r++)
                        BULK_G2S(db + r * ROW_PITCH, ts + r * C_, 1024, mb_full + 8u * slot);
                }
            }
            if (++slot == NSTAGE) { slot = 0; par ^= 1; }
        }

        // ---- acc-warps-only merge (score warps finished all slot reads earlier) ----
        asm volatile("bar.sync 1, 128;" ::: "memory");
        float* red = reinterpret_cast<float*>(dsm);   // [4][2048], absolute-c layout
#pragma unroll
        for (int h = 0; h < NH_; h++) {
            *reinterpret_cast<ull*>(&red[wa * 2048 + h * C_ + 4 * lane])           = acc2[h][0];
            *reinterpret_cast<ull*>(&red[wa * 2048 + h * C_ + 4 * lane + 2])       = acc2[h][1];
            *reinterpret_cast<ull*>(&red[wa * 2048 + h * C_ + 128 + 4 * lane])     = acc2[h][2];
            *reinterpret_cast<ull*>(&red[wa * 2048 + h * C_ + 128 + 4 * lane + 2]) = acc2[h][3];
        }
        asm volatile("bar.sync 1, 128;" ::: "memory");

        const int at = wa * 32 + lane;   // 0..127, each merges 16 floats
#pragma unroll
        for (int j = 0; j < 8; j++) {
            ull a = *reinterpret_cast<ull*>(&red[at * 16 + 2 * j]);
            a = f2add(a, *reinterpret_cast<ull*>(&red[2048 + at * 16 + 2 * j]));
            a = f2add(a, *reinterpret_cast<ull*>(&red[4096 + at * 16 + 2 * j]));
            a = f2add(a, *reinterpret_cast<ull*>(&red[6144 + at * 16 + 2 * j]));
            *reinterpret_cast<ull*>(dst + at * 16 + 2 * j) = a;
        }
    }
}

// ---------------- Kernel C: merge partials, normalize, project with Wv ----------------
__global__ void mha_combine(const float* __restrict__ Wv, const float* __restrict__ bv,
                            float* __restrict__ out) {
    const int b = blockIdx.x >> 3;
    const int h = blockIdx.x & 7;
    const int t = threadIdx.x;   // 256 threads

    __shared__ float m_s[C_];
    __shared__ float s_s[CHB * 4];
    __shared__ float gacc[4][VD_];

    const size_t base = (size_t)b * CHB * PART_STRIDE;
    float M = 0.f;
#pragma unroll
    for (int k = 0; k < CHB; k++)
        M += g_part[base + (size_t)k * PART_STRIDE + h * C_ + t];

    if (t < CHB * 4)
        s_s[t] = g_part[base + (size_t)(t >> 2) * PART_STRIDE + 2048 + (t & 3) * NH_ + h];
    __syncthreads();

    float S = 0.f;
#pragma unroll
    for (int k = 0; k < CHB * 4; k++) S += s_s[k];

    m_s[t] = M;   // unnormalized; divide once at the end
    __syncthreads();

    const int q  = t >> 6;    // c-quarter 0..3
    const int vd = t & 63;    // output dim
    float acc = 0.f;
#pragma unroll 8
    for (int i = 0; i < 64; i++) {
        int c = q * 64 + i;
        acc += m_s[c] * Wv[c * (NH_ * VD_) + h * VD_ + vd];   // coalesced across vd
    }
    gacc[q][vd] = acc;
    __syncthreads();

    if (t < VD_) {
        float r = (gacc[0][t] + gacc[1][t] + gacc[2][t] + gacc[3][t]) / S + bv[h * VD_ + t];
        out[(b * NH_ + h) * VD_ + t] = r;
    }
}

extern "C" void kernel_launch(void* const* d_in, const int* in_sizes, int n_in,
                              void* d_out, int out_size) {
    const float* kv = (const float*)d_in[0];
    const float* Wk = (const float*)d_in[1];
    // d_in[2] = bk: per-(b,h) additive constant on scores -> cancels in softmax, unused.
    const float* Wv = (const float*)d_in[3];
    const float* bv = (const float*)d_in[4];
    const float* q  = (const float*)d_in[5];
    float* out = (float*)d_out;

    cudaFuncSetAttribute(mha_main, cudaFuncAttributeMaxDynamicSharedMemorySize, SMEM_TOTAL);

    mha_prep<<<256, 256>>>(Wk, q);
    mha_main<<<NCTA, 256, SMEM_TOTAL>>>(kv);
    mha_combine<<<B_ * NH_, 256>>>(Wv, bv, out);
}